// round 1
// baseline (speedup 1.0000x reference)
#include <cuda_runtime.h>
#include <math.h>

// ---------------------------------------------------------------------------
// Attention_80642305950390
//   q = query @ Wq + bq ; k = key @ Wk + bk ; v = value @ Wv + bv
//   scores = q @ k^T / sqrt(A) ; probs = softmax(scores) ; out = probs @ v
//   B=4, S=2048, E=1024, A=1024  (all fp32)
// Round 1: fp32 register-blocked SGEMM pipeline (correctness anchor).
// ---------------------------------------------------------------------------

#define Bq 4
#define Sq 2048
#define Eq 1024
#define Aq 1024
#define MS (Bq * Sq)           // 8192 rows for QKV projections

// Scratch (device globals: allocation-free per harness rules)
__device__ float g_Q[(size_t)MS * Aq];          // 33.5 MB
__device__ float g_K[(size_t)MS * Aq];          // 33.5 MB
__device__ float g_V[(size_t)MS * Aq];          // 33.5 MB
__device__ float g_S[(size_t)Bq * Sq * Sq];     // 67 MB

#define BM 128
#define BN 128
#define BK 8
#define TM 8
#define TN 8

// ---------------------------------------------------------------------------
// Register-blocked SGEMM: C[M,N] = alpha * A[M,K] @ op(B) (+ bias)
//   TRANSB=false: B is [K,N] row-major (NN)
//   TRANSB=true : B is [N,K] row-major (NT, computes A @ B^T)
// blockIdx.z batches with the given element strides.
// All of M,N divisible by 128 and K divisible by 8 (guaranteed by shapes).
// ---------------------------------------------------------------------------
template <bool TRANSB, bool HASBIAS>
__global__ __launch_bounds__(256, 2)
void sgemm_kernel(const float* __restrict__ A, const float* __restrict__ B,
                  const float* __restrict__ bias, float* __restrict__ C,
                  int M, int N, int K, float alpha,
                  long long strideA, long long strideB, long long strideC)
{
    A += (long long)blockIdx.z * strideA;
    B += (long long)blockIdx.z * strideB;
    C += (long long)blockIdx.z * strideC;

    __shared__ float As[BK][BM];
    __shared__ float Bs[BK][BN];

    const int tid  = threadIdx.x;
    const int cRow = blockIdx.y * BM;
    const int cCol = blockIdx.x * BN;

    // A-tile load mapping: 128 rows x 8 cols, one float4 per thread
    const int aRow = tid >> 1;          // 0..127
    const int aCol = (tid & 1) << 2;    // 0 or 4
    // B-tile NN load mapping: 8 rows x 128 cols, one float4 per thread
    const int bRow = tid >> 5;          // 0..7
    const int bCol = (tid & 31) << 2;   // 0..124

    const int tx = (tid & 15) * TN;     // output col offset in tile
    const int ty = (tid >> 4) * TM;     // output row offset in tile

    float acc[TM][TN] = {};
    float regA[TM], regB[TN];

    for (int k0 = 0; k0 < K; k0 += BK) {
        // Load A tile (transpose into As[k][m])
        float4 a4 = *reinterpret_cast<const float4*>(
            &A[(long long)(cRow + aRow) * K + k0 + aCol]);
        As[aCol + 0][aRow] = a4.x;
        As[aCol + 1][aRow] = a4.y;
        As[aCol + 2][aRow] = a4.z;
        As[aCol + 3][aRow] = a4.w;

        if (TRANSB) {
            // B is [N,K]: tile covers n in [cCol,cCol+128), k in [k0,k0+8)
            float4 b4 = *reinterpret_cast<const float4*>(
                &B[(long long)(cCol + aRow) * K + k0 + aCol]);
            Bs[aCol + 0][aRow] = b4.x;
            Bs[aCol + 1][aRow] = b4.y;
            Bs[aCol + 2][aRow] = b4.z;
            Bs[aCol + 3][aRow] = b4.w;
        } else {
            // B is [K,N]: contiguous along N
            float4 b4 = *reinterpret_cast<const float4*>(
                &B[(long long)(k0 + bRow) * N + cCol + bCol]);
            *reinterpret_cast<float4*>(&Bs[bRow][bCol]) = b4;
        }
        __syncthreads();

        #pragma unroll
        for (int k = 0; k < BK; k++) {
            #pragma unroll
            for (int i = 0; i < TM; i++) regA[i] = As[k][ty + i];
            #pragma unroll
            for (int j = 0; j < TN; j++) regB[j] = Bs[k][tx + j];
            #pragma unroll
            for (int i = 0; i < TM; i++)
                #pragma unroll
                for (int j = 0; j < TN; j++)
                    acc[i][j] += regA[i] * regB[j];
        }
        __syncthreads();
    }

    // Epilogue: alpha scale, optional bias, float4 stores
    #pragma unroll
    for (int i = 0; i < TM; i++) {
        #pragma unroll
        for (int j = 0; j < TN; j += 4) {
            float4 v;
            v.x = acc[i][j + 0] * alpha;
            v.y = acc[i][j + 1] * alpha;
            v.z = acc[i][j + 2] * alpha;
            v.w = acc[i][j + 3] * alpha;
            if (HASBIAS) {
                const float4 b4 = *reinterpret_cast<const float4*>(&bias[cCol + tx + j]);
                v.x += b4.x; v.y += b4.y; v.z += b4.z; v.w += b4.w;
            }
            *reinterpret_cast<float4*>(
                &C[(long long)(cRow + ty + i) * N + cCol + tx + j]) = v;
        }
    }
}

// ---------------------------------------------------------------------------
// Row softmax over n=2048 columns, one block (256 threads) per row, in place.
// ---------------------------------------------------------------------------
__global__ __launch_bounds__(256)
void softmax_kernel(float* __restrict__ S)
{
    float* row = S + (long long)blockIdx.x * Sq;
    const int tid = threadIdx.x;
    __shared__ float red[256];

    float vals[8];
    float lmax = -INFINITY;
    #pragma unroll
    for (int i = 0; i < 8; i++) {
        vals[i] = row[tid + i * 256];
        lmax = fmaxf(lmax, vals[i]);
    }
    red[tid] = lmax;
    __syncthreads();
    for (int s = 128; s > 0; s >>= 1) {
        if (tid < s) red[tid] = fmaxf(red[tid], red[tid + s]);
        __syncthreads();
    }
    const float m = red[0];
    __syncthreads();

    float lsum = 0.0f;
    #pragma unroll
    for (int i = 0; i < 8; i++) {
        vals[i] = expf(vals[i] - m);
        lsum += vals[i];
    }
    red[tid] = lsum;
    __syncthreads();
    for (int s = 128; s > 0; s >>= 1) {
        if (tid < s) red[tid] += red[tid + s];
        __syncthreads();
    }
    const float inv = 1.0f / red[0];
    #pragma unroll
    for (int i = 0; i < 8; i++) row[tid + i * 256] = vals[i] * inv;
}

// ---------------------------------------------------------------------------
extern "C" void kernel_launch(void* const* d_in, const int* in_sizes, int n_in,
                              void* d_out, int out_size)
{
    const float* query = (const float*)d_in[0];
    const float* key   = (const float*)d_in[1];
    const float* value = (const float*)d_in[2];
    const float* Wq    = (const float*)d_in[3];
    const float* bq    = (const float*)d_in[4];
    const float* Wk    = (const float*)d_in[5];
    const float* bk    = (const float*)d_in[6];
    const float* Wv    = (const float*)d_in[7];
    const float* bv    = (const float*)d_in[8];
    float* out = (float*)d_out;

    float *pQ, *pK, *pV, *pS;
    cudaGetSymbolAddress((void**)&pQ, g_Q);
    cudaGetSymbolAddress((void**)&pK, g_K);
    cudaGetSymbolAddress((void**)&pV, g_V);
    cudaGetSymbolAddress((void**)&pS, g_S);

    const dim3 blk(256);

    // 1) QKV projections: [8192,1024] @ [1024,1024] + bias (NN)
    const dim3 gqkv(Aq / BN, MS / BM, 1);
    sgemm_kernel<false, true><<<gqkv, blk>>>(query, Wq, bq, pQ, MS, Aq, Eq, 1.0f, 0, 0, 0);
    sgemm_kernel<false, true><<<gqkv, blk>>>(key,   Wk, bk, pK, MS, Aq, Eq, 1.0f, 0, 0, 0);
    sgemm_kernel<false, true><<<gqkv, blk>>>(value, Wv, bv, pV, MS, Aq, Eq, 1.0f, 0, 0, 0);

    // 2) scores = Q @ K^T / 32 per batch (NT)
    const float inv_sqrt_d = 1.0f / 32.0f;  // 1/sqrt(1024)
    const dim3 gs(Sq / BN, Sq / BM, Bq);
    sgemm_kernel<true, false><<<gs, blk>>>(pQ, pK, nullptr, pS, Sq, Sq, Aq, inv_sqrt_d,
                                           (long long)Sq * Aq, (long long)Sq * Aq,
                                           (long long)Sq * Sq);

    // 3) softmax over rows (B*S rows of length S)
    softmax_kernel<<<Bq * Sq, blk>>>(pS);

    // 4) out = P @ V per batch (NN), directly to d_out
    const dim3 go(Aq / BN, Sq / BM, Bq);
    sgemm_kernel<false, false><<<go, blk>>>(pS, pV, nullptr, out, Sq, Aq, Sq, 1.0f,
                                            (long long)Sq * Sq, (long long)Sq * Aq,
                                            (long long)Sq * Aq);
}

// round 2
// speedup vs baseline: 2.8185x; 2.8185x over previous
#include <cuda_runtime.h>
#include <math.h>
#include <stdint.h>

// ---------------------------------------------------------------------------
// Attention_80642305950390 — round 2: tf32 mma.sync tensor-core GEMM pipeline
//   B=4, S=2048, E=1024, A=1024 (fp32 in/out, tf32 tensor math, fp32 accum)
// ---------------------------------------------------------------------------

#define Bq 4
#define Sq 2048
#define Eq 1024
#define Aq 1024
#define MS (Bq * Sq)

__device__ float g_Q[(size_t)MS * Aq];
__device__ float g_K[(size_t)MS * Aq];
__device__ float g_V[(size_t)MS * Aq];
__device__ float g_S[(size_t)Bq * Sq * Sq];

// ---------------------------------------------------------------------------
__device__ __forceinline__ void cp_async16(void* smem, const void* gmem) {
    uint32_t s = (uint32_t)__cvta_generic_to_shared(smem);
    asm volatile("cp.async.cg.shared.global [%0], [%1], 16;\n" :: "r"(s), "l"(gmem));
}
#define CP_COMMIT() asm volatile("cp.async.commit_group;\n" ::: "memory")
#define CP_WAIT0()  asm volatile("cp.async.wait_group 0;\n" ::: "memory")

__device__ __forceinline__ uint32_t f2tf32(float x) {
    uint32_t r;
    asm("cvt.rna.tf32.f32 %0, %1;" : "=r"(r) : "f"(x));
    return r;
}

__device__ __forceinline__ void mma_tf32(float* d, const uint32_t* a,
                                         uint32_t b0, uint32_t b1) {
    asm volatile(
        "mma.sync.aligned.m16n8k8.row.col.f32.tf32.tf32.f32 "
        "{%0,%1,%2,%3},{%4,%5,%6,%7},{%8,%9},{%0,%1,%2,%3};"
        : "+f"(d[0]), "+f"(d[1]), "+f"(d[2]), "+f"(d[3])
        : "r"(a[0]), "r"(a[1]), "r"(a[2]), "r"(a[3]), "r"(b0), "r"(b1));
}

// ---------------------------------------------------------------------------
// tf32 GEMM: C[M,N] = alpha * A[M,K] @ op(B) (+ bias)
//   TRANSB=false: B[K,N] (NN) ; TRANSB=true: B[N,K] (NT)
// Tiles: BM=BN=128, BK=16. 256 threads, 8 warps (4 M x 2 N), 32x64 per warp.
// All dims exact multiples (M%128==0, N%128==0, K%16==0).
// ---------------------------------------------------------------------------
template <bool TRANSB, bool HASBIAS>
__global__ __launch_bounds__(256, 2)
void tf32_gemm(const float* __restrict__ A, const float* __restrict__ B,
               const float* __restrict__ bias, float* __restrict__ C,
               int M, int N, int K, float alpha,
               long long sA, long long sB, long long sC)
{
    A += (long long)blockIdx.z * sA;
    B += (long long)blockIdx.z * sB;
    C += (long long)blockIdx.z * sC;

    // A: [128 rows][16 k + pad4]  (stride 20 -> conflict-free fragment loads)
    // B NN: [16 k][128 n + pad8]  (stride 136)
    // B NT: [128 n][16 k + pad4]  (stride 20)
    __shared__ float As[2][128][20];
    __shared__ float Bs[2][2560];   // max(16*136=2176, 128*20=2560)

    const int tid  = threadIdx.x;
    const int wid  = tid >> 5;
    const int lane = tid & 31;
    const int wm   = wid >> 1;      // 0..3  (M direction, 32 rows each)
    const int wn   = wid & 1;       // 0..1  (N direction, 64 cols each)
    const int g    = lane >> 2;     // group 0..7
    const int t    = lane & 3;      // thread-in-group 0..3
    const int cRow = blockIdx.y * 128;
    const int cCol = blockIdx.x * 128;

    float acc[2][8][4];
    #pragma unroll
    for (int i = 0; i < 2; i++)
        #pragma unroll
        for (int j = 0; j < 8; j++)
            #pragma unroll
            for (int r = 0; r < 4; r++) acc[i][j][r] = 0.0f;

    const int NK = K >> 4;

    auto load_tiles = [&](int buf, int k0) {
        #pragma unroll
        for (int c = 0; c < 2; c++) {
            const int ch  = tid * 2 + c;          // 0..511
            const int row = ch >> 2;              // 0..127
            const int kp  = (ch & 3) << 2;        // 0,4,8,12
            cp_async16(&As[buf][row][kp],
                       &A[(long long)(cRow + row) * K + k0 + kp]);
            if (TRANSB) {
                cp_async16(&Bs[buf][row * 20 + kp],
                           &B[(long long)(cCol + row) * K + k0 + kp]);
            } else {
                const int br = ch >> 5;           // 0..15
                const int bc = (ch & 31) << 2;    // 0..124
                cp_async16(&Bs[buf][br * 136 + bc],
                           &B[(long long)(k0 + br) * N + cCol + bc]);
            }
        }
    };

    load_tiles(0, 0);
    CP_COMMIT();

    int cur = 0;
    for (int kt = 0; kt < NK; kt++) {
        CP_WAIT0();
        __syncthreads();
        if (kt + 1 < NK) {
            load_tiles(cur ^ 1, (kt + 1) << 4);
            CP_COMMIT();
        }

        // compute on buffer `cur`: two k8 sub-steps
        #pragma unroll
        for (int s = 0; s < 2; s++) {
            const int ks = s * 8;
            uint32_t af[2][4];
            #pragma unroll
            for (int mi = 0; mi < 2; mi++) {
                const int ar = wm * 32 + mi * 16 + g;
                af[mi][0] = f2tf32(As[cur][ar    ][ks + t    ]);
                af[mi][1] = f2tf32(As[cur][ar + 8][ks + t    ]);
                af[mi][2] = f2tf32(As[cur][ar    ][ks + t + 4]);
                af[mi][3] = f2tf32(As[cur][ar + 8][ks + t + 4]);
            }
            #pragma unroll
            for (int ni = 0; ni < 8; ni++) {
                const int col = wn * 64 + ni * 8 + g;
                uint32_t b0, b1;
                if (TRANSB) {
                    b0 = f2tf32(Bs[cur][col * 20 + ks + t    ]);
                    b1 = f2tf32(Bs[cur][col * 20 + ks + t + 4]);
                } else {
                    b0 = f2tf32(Bs[cur][(ks + t    ) * 136 + col]);
                    b1 = f2tf32(Bs[cur][(ks + t + 4) * 136 + col]);
                }
                #pragma unroll
                for (int mi = 0; mi < 2; mi++)
                    mma_tf32(acc[mi][ni], af[mi], b0, b1);
            }
        }
        __syncthreads();
        cur ^= 1;
    }

    // Epilogue: alpha, optional bias, float2 stores
    #pragma unroll
    for (int mi = 0; mi < 2; mi++) {
        const int row0 = cRow + wm * 32 + mi * 16 + g;
        #pragma unroll
        for (int ni = 0; ni < 8; ni++) {
            const int col = cCol + wn * 64 + ni * 8 + t * 2;
            float bx = 0.0f, by = 0.0f;
            if (HASBIAS) { bx = bias[col]; by = bias[col + 1]; }
            float2 v0, v1;
            v0.x = acc[mi][ni][0] * alpha + bx;
            v0.y = acc[mi][ni][1] * alpha + by;
            v1.x = acc[mi][ni][2] * alpha + bx;
            v1.y = acc[mi][ni][3] * alpha + by;
            *reinterpret_cast<float2*>(&C[(long long)row0 * N + col]) = v0;
            *reinterpret_cast<float2*>(&C[(long long)(row0 + 8) * N + col]) = v1;
        }
    }
}

// ---------------------------------------------------------------------------
// Row softmax over 2048 columns, one block (256 threads) per row, in place.
// ---------------------------------------------------------------------------
__global__ __launch_bounds__(256)
void softmax_kernel(float* __restrict__ S)
{
    float* row = S + (long long)blockIdx.x * Sq;
    const int tid = threadIdx.x;
    __shared__ float red[256];

    float vals[8];
    float lmax = -INFINITY;
    #pragma unroll
    for (int i = 0; i < 8; i++) {
        vals[i] = row[tid + i * 256];
        lmax = fmaxf(lmax, vals[i]);
    }
    red[tid] = lmax;
    __syncthreads();
    for (int s = 128; s > 0; s >>= 1) {
        if (tid < s) red[tid] = fmaxf(red[tid], red[tid + s]);
        __syncthreads();
    }
    const float m = red[0];
    __syncthreads();

    float lsum = 0.0f;
    #pragma unroll
    for (int i = 0; i < 8; i++) {
        vals[i] = expf(vals[i] - m);
        lsum += vals[i];
    }
    red[tid] = lsum;
    __syncthreads();
    for (int s = 128; s > 0; s >>= 1) {
        if (tid < s) red[tid] += red[tid + s];
        __syncthreads();
    }
    const float inv = 1.0f / red[0];
    #pragma unroll
    for (int i = 0; i < 8; i++) row[tid + i * 256] = vals[i] * inv;
}

// ---------------------------------------------------------------------------
extern "C" void kernel_launch(void* const* d_in, const int* in_sizes, int n_in,
                              void* d_out, int out_size)
{
    const float* query = (const float*)d_in[0];
    const float* key   = (const float*)d_in[1];
    const float* value = (const float*)d_in[2];
    const float* Wq    = (const float*)d_in[3];
    const float* bq    = (const float*)d_in[4];
    const float* Wk    = (const float*)d_in[5];
    const float* bk    = (const float*)d_in[6];
    const float* Wv    = (const float*)d_in[7];
    const float* bv    = (const float*)d_in[8];
    float* out = (float*)d_out;

    float *pQ, *pK, *pV, *pS;
    cudaGetSymbolAddress((void**)&pQ, g_Q);
    cudaGetSymbolAddress((void**)&pK, g_K);
    cudaGetSymbolAddress((void**)&pV, g_V);
    cudaGetSymbolAddress((void**)&pS, g_S);

    const dim3 blk(256);

    // 1) QKV projections (NN + bias): [8192,1024] @ [1024,1024]
    const dim3 gqkv(Aq / 128, MS / 128, 1);
    tf32_gemm<false, true><<<gqkv, blk>>>(query, Wq, bq, pQ, MS, Aq, Eq, 1.0f, 0, 0, 0);
    tf32_gemm<false, true><<<gqkv, blk>>>(key,   Wk, bk, pK, MS, Aq, Eq, 1.0f, 0, 0, 0);
    tf32_gemm<false, true><<<gqkv, blk>>>(value, Wv, bv, pV, MS, Aq, Eq, 1.0f, 0, 0, 0);

    // 2) scores = Q @ K^T / 32 per batch (NT)
    const dim3 gs(Sq / 128, Sq / 128, Bq);
    tf32_gemm<true, false><<<gs, blk>>>(pQ, pK, nullptr, pS, Sq, Sq, Aq, 1.0f / 32.0f,
                                        (long long)Sq * Aq, (long long)Sq * Aq,
                                        (long long)Sq * Sq);

    // 3) softmax rows
    softmax_kernel<<<Bq * Sq, blk>>>(pS);

    // 4) out = P @ V per batch (NN) -> d_out
    const dim3 go(Aq / 128, Sq / 128, Bq);
    tf32_gemm<false, false><<<go, blk>>>(pS, pV, nullptr, out, Sq, Aq, Sq, 1.0f,
                                         (long long)Sq * Sq, (long long)Sq * Aq,
                                         (long long)Sq * Aq);
}

// round 3
// speedup vs baseline: 2.8293x; 1.0038x over previous
#include <cuda_runtime.h>
#include <math.h>
#include <stdint.h>

// ---------------------------------------------------------------------------
// Attention_80642305950390 — round 3: tf32 mma.sync, no in-loop CVT,
// 4-stage cp.async pipeline. B=4, S=2048, E=1024, A=1024.
// ---------------------------------------------------------------------------

#define Bq 4
#define Sq 2048
#define Eq 1024
#define Aq 1024
#define MS (Bq * Sq)

// Scratch
__device__ float g_Q[(size_t)MS * Aq];
__device__ float g_K[(size_t)MS * Aq];
__device__ float g_V[(size_t)MS * Aq];
__device__ float g_S[(size_t)Bq * Sq * Sq];
// Pre-rounded (tf32) copies of inputs
__device__ float g_qr[(size_t)MS * Eq];
__device__ float g_kr[(size_t)MS * Eq];
__device__ float g_vr[(size_t)MS * Eq];
__device__ float g_Wqr[(size_t)Eq * Aq];
__device__ float g_Wkr[(size_t)Eq * Aq];
__device__ float g_Wvr[(size_t)Eq * Aq];

// ---------------------------------------------------------------------------
__device__ __forceinline__ void cp_async16(void* smem, const void* gmem) {
    uint32_t s = (uint32_t)__cvta_generic_to_shared(smem);
    asm volatile("cp.async.cg.shared.global [%0], [%1], 16;\n" :: "r"(s), "l"(gmem));
}
#define CP_COMMIT() asm volatile("cp.async.commit_group;\n" ::: "memory")
#define CP_WAIT(N)  asm volatile("cp.async.wait_group %0;\n" :: "n"(N) : "memory")

__device__ __forceinline__ float rna_tf32(float x) {
    uint32_t r;
    asm("cvt.rna.tf32.f32 %0, %1;" : "=r"(r) : "f"(x));
    return __uint_as_float(r);
}

__device__ __forceinline__ void mma_tf32(float* d, const uint32_t* a,
                                         uint32_t b0, uint32_t b1) {
    asm volatile(
        "mma.sync.aligned.m16n8k8.row.col.f32.tf32.tf32.f32 "
        "{%0,%1,%2,%3},{%4,%5,%6,%7},{%8,%9},{%0,%1,%2,%3};"
        : "+f"(d[0]), "+f"(d[1]), "+f"(d[2]), "+f"(d[3])
        : "r"(a[0]), "r"(a[1]), "r"(a[2]), "r"(a[3]), "r"(b0), "r"(b1));
}

// ---------------------------------------------------------------------------
// Pre-round a buffer to tf32 (rna), out-of-place. n4 = count of float4.
// ---------------------------------------------------------------------------
__global__ __launch_bounds__(256)
void round_tf32_kernel(const float* __restrict__ in, float* __restrict__ out, int n4)
{
    int i = blockIdx.x * blockDim.x + threadIdx.x;
    if (i < n4) {
        float4 v = reinterpret_cast<const float4*>(in)[i];
        v.x = rna_tf32(v.x); v.y = rna_tf32(v.y);
        v.z = rna_tf32(v.z); v.w = rna_tf32(v.w);
        reinterpret_cast<float4*>(out)[i] = v;
    }
}

// ---------------------------------------------------------------------------
// tf32 GEMM, inputs already tf32-rounded in GMEM. C = alpha*A@op(B) (+bias).
//   TRANSB=false: B[K,N] (NN) ; TRANSB=true: B[N,K] (NT)
//   ROUND_OUT: round the stored result to tf32 (rna) — for Q/K/V.
// Tiles: 128x128xBK16, 4-stage cp.async ring, 256 thr, 8 warps (4M x 2N),
// warp tile 32x64. Dims: M%128==0, N%128==0, K%16==0, K/16 >= 3.
// Dynamic smem: 4 stages * (2560 + 2560) floats = 81920 bytes.
// ---------------------------------------------------------------------------
#define STAGE_F 5120
#define SMEM_BYTES (4 * STAGE_F * 4)

template <bool TRANSB, bool HASBIAS, bool ROUND_OUT>
__global__ __launch_bounds__(256, 2)
void tf32_gemm(const float* __restrict__ A, const float* __restrict__ B,
               const float* __restrict__ bias, float* __restrict__ C,
               int M, int N, int K, float alpha,
               long long sA, long long sB, long long sC)
{
    extern __shared__ float smem[];

    A += (long long)blockIdx.z * sA;
    B += (long long)blockIdx.z * sB;
    C += (long long)blockIdx.z * sC;

    const int tid  = threadIdx.x;
    const int lane = tid & 31;
    const int wid  = tid >> 5;
    const int wm   = wid >> 1;      // 0..3
    const int wn   = wid & 1;       // 0..1
    const int g    = lane >> 2;     // 0..7
    const int t    = lane & 3;      // 0..3
    const int cRow = blockIdx.y * 128;
    const int cCol = blockIdx.x * 128;

    float acc[2][8][4];
    #pragma unroll
    for (int i = 0; i < 2; i++)
        #pragma unroll
        for (int j = 0; j < 8; j++)
            #pragma unroll
            for (int r = 0; r < 4; r++) acc[i][j][r] = 0.0f;

    const int NK = K >> 4;

    // Staging: A as [128][20] (stride 20), B NT as [128][20], B NN as [16][136].
    auto load_tiles = [&](int stage, int k0) {
        float* As = smem + stage * STAGE_F;
        float* Bs = As + 2560;
        #pragma unroll
        for (int c = 0; c < 2; c++) {
            const int ch  = tid * 2 + c;          // 0..511
            const int row = ch >> 2;              // 0..127
            const int kp  = (ch & 3) << 2;        // 0,4,8,12
            cp_async16(&As[row * 20 + kp],
                       &A[(long long)(cRow + row) * K + k0 + kp]);
            if (TRANSB) {
                cp_async16(&Bs[row * 20 + kp],
                           &B[(long long)(cCol + row) * K + k0 + kp]);
            } else {
                const int br = ch >> 5;           // 0..15
                const int bc = (ch & 31) << 2;    // 0..124
                cp_async16(&Bs[br * 136 + bc],
                           &B[(long long)(k0 + br) * N + cCol + bc]);
            }
        }
    };

    // Prologue: 3 tiles in flight.
    load_tiles(0, 0);  CP_COMMIT();
    load_tiles(1, 16); CP_COMMIT();
    load_tiles(2, 32); CP_COMMIT();

    for (int kt = 0; kt < NK; kt++) {
        CP_WAIT(2);
        __syncthreads();

        const float* As = smem + (kt & 3) * STAGE_F;
        const float* Bs = As + 2560;

        #pragma unroll
        for (int s = 0; s < 2; s++) {
            const int ks = s * 8;
            uint32_t af[2][4];
            #pragma unroll
            for (int mi = 0; mi < 2; mi++) {
                const int ar = wm * 32 + mi * 16 + g;
                af[mi][0] = __float_as_uint(As[(ar    ) * 20 + ks + t    ]);
                af[mi][1] = __float_as_uint(As[(ar + 8) * 20 + ks + t    ]);
                af[mi][2] = __float_as_uint(As[(ar    ) * 20 + ks + t + 4]);
                af[mi][3] = __float_as_uint(As[(ar + 8) * 20 + ks + t + 4]);
            }
            #pragma unroll
            for (int ni = 0; ni < 8; ni++) {
                const int col = wn * 64 + ni * 8 + g;
                uint32_t b0, b1;
                if (TRANSB) {
                    b0 = __float_as_uint(Bs[col * 20 + ks + t    ]);
                    b1 = __float_as_uint(Bs[col * 20 + ks + t + 4]);
                } else {
                    b0 = __float_as_uint(Bs[(ks + t    ) * 136 + col]);
                    b1 = __float_as_uint(Bs[(ks + t + 4) * 136 + col]);
                }
                #pragma unroll
                for (int mi = 0; mi < 2; mi++)
                    mma_tf32(acc[mi][ni], af[mi], b0, b1);
            }
        }
        __syncthreads();

        if (kt + 3 < NK) load_tiles((kt + 3) & 3, (kt + 3) << 4);
        CP_COMMIT();   // always commit to keep group accounting aligned
    }

    // Epilogue
    #pragma unroll
    for (int mi = 0; mi < 2; mi++) {
        const int row0 = cRow + wm * 32 + mi * 16 + g;
        #pragma unroll
        for (int ni = 0; ni < 8; ni++) {
            const int col = cCol + wn * 64 + ni * 8 + t * 2;
            float bx = 0.0f, by = 0.0f;
            if (HASBIAS) { bx = bias[col]; by = bias[col + 1]; }
            float2 v0, v1;
            v0.x = acc[mi][ni][0] * alpha + bx;
            v0.y = acc[mi][ni][1] * alpha + by;
            v1.x = acc[mi][ni][2] * alpha + bx;
            v1.y = acc[mi][ni][3] * alpha + by;
            if (ROUND_OUT) {
                v0.x = rna_tf32(v0.x); v0.y = rna_tf32(v0.y);
                v1.x = rna_tf32(v1.x); v1.y = rna_tf32(v1.y);
            }
            *reinterpret_cast<float2*>(&C[(long long)row0 * N + col]) = v0;
            *reinterpret_cast<float2*>(&C[(long long)(row0 + 8) * N + col]) = v1;
        }
    }
}

// ---------------------------------------------------------------------------
// Row softmax over 2048 cols, one block per row, in place.
// Stores probs pre-rounded to tf32 (consumed by the PV GEMM).
// ---------------------------------------------------------------------------
__global__ __launch_bounds__(256)
void softmax_kernel(float* __restrict__ S)
{
    float* row = S + (long long)blockIdx.x * Sq;
    const int tid = threadIdx.x;
    __shared__ float red[256];

    float vals[8];
    float lmax = -INFINITY;
    #pragma unroll
    for (int i = 0; i < 8; i++) {
        vals[i] = row[tid + i * 256];
        lmax = fmaxf(lmax, vals[i]);
    }
    red[tid] = lmax;
    __syncthreads();
    for (int s = 128; s > 0; s >>= 1) {
        if (tid < s) red[tid] = fmaxf(red[tid], red[tid + s]);
        __syncthreads();
    }
    const float m = red[0];
    __syncthreads();

    float lsum = 0.0f;
    #pragma unroll
    for (int i = 0; i < 8; i++) {
        vals[i] = expf(vals[i] - m);
        lsum += vals[i];
    }
    red[tid] = lsum;
    __syncthreads();
    for (int s = 128; s > 0; s >>= 1) {
        if (tid < s) red[tid] += red[tid + s];
        __syncthreads();
    }
    const float inv = 1.0f / red[0];
    #pragma unroll
    for (int i = 0; i < 8; i++) row[tid + i * 256] = rna_tf32(vals[i] * inv);
}

// ---------------------------------------------------------------------------
extern "C" void kernel_launch(void* const* d_in, const int* in_sizes, int n_in,
                              void* d_out, int out_size)
{
    const float* query = (const float*)d_in[0];
    const float* key   = (const float*)d_in[1];
    const float* value = (const float*)d_in[2];
    const float* Wq    = (const float*)d_in[3];
    const float* bq    = (const float*)d_in[4];
    const float* Wk    = (const float*)d_in[5];
    const float* bk    = (const float*)d_in[6];
    const float* Wv    = (const float*)d_in[7];
    const float* bv    = (const float*)d_in[8];
    float* out = (float*)d_out;

    float *pQ, *pK, *pV, *pS, *pqr, *pkr, *pvr, *pWq, *pWk, *pWv;
    cudaGetSymbolAddress((void**)&pQ,  g_Q);
    cudaGetSymbolAddress((void**)&pK,  g_K);
    cudaGetSymbolAddress((void**)&pV,  g_V);
    cudaGetSymbolAddress((void**)&pS,  g_S);
    cudaGetSymbolAddress((void**)&pqr, g_qr);
    cudaGetSymbolAddress((void**)&pkr, g_kr);
    cudaGetSymbolAddress((void**)&pvr, g_vr);
    cudaGetSymbolAddress((void**)&pWq, g_Wqr);
    cudaGetSymbolAddress((void**)&pWk, g_Wkr);
    cudaGetSymbolAddress((void**)&pWv, g_Wvr);

    // Opt in to 80KB dynamic smem (idempotent; host-side, capture-safe).
    static bool attr_done = false;
    if (!attr_done) {
        cudaFuncSetAttribute(tf32_gemm<false, true,  true >, cudaFuncAttributeMaxDynamicSharedMemorySize, SMEM_BYTES);
        cudaFuncSetAttribute(tf32_gemm<true,  false, false>, cudaFuncAttributeMaxDynamicSharedMemorySize, SMEM_BYTES);
        cudaFuncSetAttribute(tf32_gemm<false, false, false>, cudaFuncAttributeMaxDynamicSharedMemorySize, SMEM_BYTES);
        attr_done = true;
    }

    const dim3 blk(256);

    // 0) Pre-round inputs to tf32 (rna)
    {
        const int nin  = MS * Eq / 4;    // 2,097,152 float4
        const int nw   = Eq * Aq / 4;    // 262,144 float4
        round_tf32_kernel<<<(nin + 255) / 256, blk>>>(query, pqr, nin);
        round_tf32_kernel<<<(nin + 255) / 256, blk>>>(key,   pkr, nin);
        round_tf32_kernel<<<(nin + 255) / 256, blk>>>(value, pvr, nin);
        round_tf32_kernel<<<(nw  + 255) / 256, blk>>>(Wq, pWq, nw);
        round_tf32_kernel<<<(nw  + 255) / 256, blk>>>(Wk, pWk, nw);
        round_tf32_kernel<<<(nw  + 255) / 256, blk>>>(Wv, pWv, nw);
    }

    // 1) QKV projections (NN + bias), outputs rounded to tf32
    const dim3 gqkv(Aq / 128, MS / 128, 1);
    tf32_gemm<false, true, true><<<gqkv, blk, SMEM_BYTES>>>(pqr, pWq, bq, pQ, MS, Aq, Eq, 1.0f, 0, 0, 0);
    tf32_gemm<false, true, true><<<gqkv, blk, SMEM_BYTES>>>(pkr, pWk, bk, pK, MS, Aq, Eq, 1.0f, 0, 0, 0);
    tf32_gemm<false, true, true><<<gqkv, blk, SMEM_BYTES>>>(pvr, pWv, bv, pV, MS, Aq, Eq, 1.0f, 0, 0, 0);

    // 2) scores = Q @ K^T / 32 per batch (NT), fp32 output
    const dim3 gs(Sq / 128, Sq / 128, Bq);
    tf32_gemm<true, false, false><<<gs, blk, SMEM_BYTES>>>(pQ, pK, nullptr, pS, Sq, Sq, Aq, 1.0f / 32.0f,
                                        (long long)Sq * Aq, (long long)Sq * Aq,
                                        (long long)Sq * Sq);

    // 3) softmax rows (stores tf32-rounded probs)
    softmax_kernel<<<Bq * Sq, blk>>>(pS);

    // 4) out = P @ V per batch (NN) -> d_out (fp32)
    const dim3 go(Aq / 128, Sq / 128, Bq);
    tf32_gemm<false, false, false><<<go, blk, SMEM_BYTES>>>(pS, pV, nullptr, out, Sq, Aq, Sq, 1.0f,
                                         (long long)Sq * Sq, (long long)Sq * Aq,
                                         (long long)Sq * Aq);
}

// round 5
// speedup vs baseline: 4.2557x; 1.5042x over previous
#include <cuda_runtime.h>
#include <math.h>
#include <stdint.h>

// ---------------------------------------------------------------------------
// Attention_80642305950390 — round 5: legacy mma.sync tf32, 64x64 warp tile,
// ldmatrix fragment loads, all GEMMs NT, 4-stage cp.async ring.
//   B=4, S=2048, E=1024, A=1024. (tcgen05 unavailable: harness targets sm_103)
// ---------------------------------------------------------------------------

#define Bq 4
#define Sq 2048
#define Eq 1024
#define Aq 1024
#define MS (Bq * Sq)

// Scratch
__device__ float g_Q [(size_t)MS * Aq];
__device__ float g_K [(size_t)MS * Aq];
__device__ float g_V [(size_t)MS * Aq];
__device__ float g_Vt[(size_t)MS * Aq];      // per-batch V^T: [b][A][S]
__device__ float g_S [(size_t)Bq * Sq * Sq];
__device__ float g_qr[(size_t)MS * Eq];
__device__ float g_kr[(size_t)MS * Eq];
__device__ float g_vr[(size_t)MS * Eq];
__device__ float g_Wqt[(size_t)Eq * Aq];     // rna(W)^T [A][E]
__device__ float g_Wkt[(size_t)Eq * Aq];
__device__ float g_Wvt[(size_t)Eq * Aq];

// ---------------------------------------------------------------------------
__device__ __forceinline__ uint32_t smem_u32(const void* p) {
    uint32_t a;
    asm("{ .reg .u64 t; cvta.to.shared.u64 t, %1; cvt.u32.u64 %0, t; }"
        : "=r"(a) : "l"(p));
    return a;
}
__device__ __forceinline__ void cp_async16(uint32_t smem, const void* gmem) {
    asm volatile("cp.async.cg.shared.global [%0], [%1], 16;\n" :: "r"(smem), "l"(gmem));
}
#define CP_COMMIT() asm volatile("cp.async.commit_group;\n" ::: "memory")
#define CP_WAIT(N)  asm volatile("cp.async.wait_group %0;\n" :: "n"(N) : "memory")

__device__ __forceinline__ float rna_tf32(float x) {
    uint32_t r;
    asm("cvt.rna.tf32.f32 %0, %1;" : "=r"(r) : "f"(x));
    return __uint_as_float(r);
}
__device__ __forceinline__ void ldsm_x4(uint32_t addr, uint32_t* r) {
    asm volatile("ldmatrix.sync.aligned.m8n8.x4.shared.b16 {%0,%1,%2,%3}, [%4];"
                 : "=r"(r[0]), "=r"(r[1]), "=r"(r[2]), "=r"(r[3]) : "r"(addr));
}
__device__ __forceinline__ void mma_tf32(float* d, const uint32_t* a,
                                         uint32_t b0, uint32_t b1) {
    asm volatile(
        "mma.sync.aligned.m16n8k8.row.col.f32.tf32.tf32.f32 "
        "{%0,%1,%2,%3},{%4,%5,%6,%7},{%8,%9},{%0,%1,%2,%3};"
        : "+f"(d[0]), "+f"(d[1]), "+f"(d[2]), "+f"(d[3])
        : "r"(a[0]), "r"(a[1]), "r"(a[2]), "r"(a[3]), "r"(b0), "r"(b1));
}

// ---------------------------------------------------------------------------
// NT tf32 GEMM: C[M,N] = alpha * A[M,K] @ B[N,K]^T (+bias, +rna round-out)
// CTA tile 128x128xBK16, 4 warps (128 thr), warp tile 64x64, 4-stage ring.
// smem rows stride 20 floats (80B): ldmatrix + cp.async conflict-free.
// Requires M,N %128==0, K%16==0, K/16 >= 3.
// ---------------------------------------------------------------------------
#define ROW_F 20
#define ROW_B 80
#define AB_PAD_BYTES (128 * ROW_B)            // 10240
#define STAGE_BYTES (2 * AB_PAD_BYTES)        // 20480
#define GEMM_SMEM (4 * STAGE_BYTES)           // 81920

template <bool HASBIAS, bool ROUND_OUT>
__global__ __launch_bounds__(128, 2)
void tf32_gemm_nt(const float* __restrict__ A, const float* __restrict__ B,
                  const float* __restrict__ bias, float* __restrict__ C,
                  int N, int K, float alpha,
                  long long sA, long long sB, long long sC)
{
    extern __shared__ char smem[];
    const uint32_t smem_base = smem_u32(smem);

    A += (long long)blockIdx.z * sA;
    B += (long long)blockIdx.z * sB;
    C += (long long)blockIdx.z * sC;

    const int tid  = threadIdx.x;
    const int lane = tid & 31;
    const int wid  = tid >> 5;
    const int wm   = wid >> 1;            // 0..1
    const int wn   = wid & 1;             // 0..1
    const int g    = lane >> 2;
    const int t    = lane & 3;
    const int cRow = blockIdx.y * 128;
    const int cCol = blockIdx.x * 128;

    // ldmatrix per-lane byte offsets (within A / B region of a stage)
    // A x4 tiles: rows (lane&15), k-offset 4*(lane>>4)   [16 rows x 8 k]
    const uint32_t a_lane = (uint32_t)(((wm * 64 + (lane & 15)) * ROW_F
                                        + ((lane >> 4) << 2)) * 4);
    // B x4 tiles: rows (lane&7)+8*((lane>>4)&1), k-offset 4*((lane>>3)&1)
    const uint32_t b_lane = (uint32_t)(((wn * 64 + (lane & 7) + ((lane >> 4) & 1) * 8) * ROW_F
                                        + (((lane >> 3) & 1) << 2)) * 4);

    float acc[4][8][4];
    #pragma unroll
    for (int i = 0; i < 4; i++)
        #pragma unroll
        for (int j = 0; j < 8; j++)
            #pragma unroll
            for (int r = 0; r < 4; r++) acc[i][j][r] = 0.0f;

    const int NK = K >> 4;

    auto load_tile = [&](int stage, int kt) {
        const uint32_t As = smem_base + stage * STAGE_BYTES;
        const uint32_t Bs = As + AB_PAD_BYTES;
        const long long kbase = (long long)(kt << 4);
        #pragma unroll
        for (int i = 0; i < 4; i++) {
            const int ch  = tid + i * 128;      // 0..511
            const int row = ch >> 2;            // 0..127
            const int k4  = ch & 3;             // 16B chunk
            const uint32_t so = (uint32_t)(row * ROW_B + k4 * 16);
            cp_async16(As + so, &A[(long long)(cRow + row) * K + kbase + k4 * 4]);
            cp_async16(Bs + so, &B[(long long)(cCol + row) * K + kbase + k4 * 4]);
        }
    };

    load_tile(0, 0); CP_COMMIT();
    load_tile(1, 1); CP_COMMIT();
    load_tile(2, 2); CP_COMMIT();

    for (int kt = 0; kt < NK; kt++) {
        CP_WAIT(2);
        __syncthreads();

        if (kt + 3 < NK) load_tile((kt + 3) & 3, kt + 3);
        CP_COMMIT();

        const uint32_t sA_base = smem_base + (kt & 3) * STAGE_BYTES + a_lane;
        const uint32_t sB_base = smem_base + (kt & 3) * STAGE_BYTES + AB_PAD_BYTES + b_lane;

        #pragma unroll
        for (int s = 0; s < 2; s++) {
            const uint32_t ko = s * 32;         // ks*4 bytes (ks = 0 or 8)
            uint32_t a[4][4], b[4][4];
            #pragma unroll
            for (int mi = 0; mi < 4; mi++)
                ldsm_x4(sA_base + mi * (16 * ROW_B) + ko, a[mi]);
            #pragma unroll
            for (int p = 0; p < 4; p++)
                ldsm_x4(sB_base + p * (16 * ROW_B) + ko, b[p]);
            #pragma unroll
            for (int p = 0; p < 4; p++)
                #pragma unroll
                for (int mi = 0; mi < 4; mi++) {
                    mma_tf32(acc[mi][2 * p    ], a[mi], b[p][0], b[p][1]);
                    mma_tf32(acc[mi][2 * p + 1], a[mi], b[p][2], b[p][3]);
                }
        }
    }

    // Epilogue
    #pragma unroll
    for (int mi = 0; mi < 4; mi++) {
        const int row0 = cRow + wm * 64 + mi * 16 + g;
        #pragma unroll
        for (int ni = 0; ni < 8; ni++) {
            const int col = cCol + wn * 64 + ni * 8 + t * 2;
            float bx = 0.0f, by = 0.0f;
            if (HASBIAS) {
                const float2 b2 = *reinterpret_cast<const float2*>(&bias[col]);
                bx = b2.x; by = b2.y;
            }
            float2 v0, v1;
            v0.x = acc[mi][ni][0] * alpha + bx;
            v0.y = acc[mi][ni][1] * alpha + by;
            v1.x = acc[mi][ni][2] * alpha + bx;
            v1.y = acc[mi][ni][3] * alpha + by;
            if (ROUND_OUT) {
                v0.x = rna_tf32(v0.x); v0.y = rna_tf32(v0.y);
                v1.x = rna_tf32(v1.x); v1.y = rna_tf32(v1.y);
            }
            *reinterpret_cast<float2*>(&C[(long long)row0 * N + col]) = v0;
            *reinterpret_cast<float2*>(&C[(long long)(row0 + 8) * N + col]) = v1;
        }
    }
}

// ---------------------------------------------------------------------------
// Elementwise rna round (float4)
// ---------------------------------------------------------------------------
__global__ __launch_bounds__(256)
void round_tf32_kernel(const float* __restrict__ in, float* __restrict__ out, int n4)
{
    int i = blockIdx.x * blockDim.x + threadIdx.x;
    if (i < n4) {
        float4 v = reinterpret_cast<const float4*>(in)[i];
        v.x = rna_tf32(v.x); v.y = rna_tf32(v.y);
        v.z = rna_tf32(v.z); v.w = rna_tf32(v.w);
        reinterpret_cast<float4*>(out)[i] = v;
    }
}

// ---------------------------------------------------------------------------
// W transpose + rna: in [E,A] -> out [A,E]
// ---------------------------------------------------------------------------
__global__ __launch_bounds__(256)
void transpose_round_kernel(const float* __restrict__ in, float* __restrict__ out)
{
    __shared__ float tbuf[32][33];
    const int tx = threadIdx.x, ty = threadIdx.y;
    const int a0 = blockIdx.x * 32;
    const int e0 = blockIdx.y * 32;
    #pragma unroll
    for (int r = 0; r < 4; r++)
        tbuf[ty + r * 8][tx] = rna_tf32(in[(long long)(e0 + ty + r * 8) * Aq + a0 + tx]);
    __syncthreads();
    #pragma unroll
    for (int r = 0; r < 4; r++)
        out[(long long)(a0 + ty + r * 8) * Eq + e0 + tx] = tbuf[tx][ty + r * 8];
}

// ---------------------------------------------------------------------------
// Batched exact transpose: in [B][S][A] -> out [B][A][S]
// ---------------------------------------------------------------------------
__global__ __launch_bounds__(256)
void transpose_batched_kernel(const float* __restrict__ in, float* __restrict__ out)
{
    __shared__ float tbuf[32][33];
    const int tx = threadIdx.x, ty = threadIdx.y;
    const int a0 = blockIdx.x * 32;
    const int s0 = blockIdx.y * 32;
    const long long bo_in  = (long long)blockIdx.z * Sq * Aq;
    const long long bo_out = (long long)blockIdx.z * Aq * Sq;
    #pragma unroll
    for (int r = 0; r < 4; r++)
        tbuf[ty + r * 8][tx] = in[bo_in + (long long)(s0 + ty + r * 8) * Aq + a0 + tx];
    __syncthreads();
    #pragma unroll
    for (int r = 0; r < 4; r++)
        out[bo_out + (long long)(a0 + ty + r * 8) * Sq + s0 + tx] = tbuf[tx][ty + r * 8];
}

// ---------------------------------------------------------------------------
// Row softmax over 2048 cols, in place; stores tf32-rounded probs.
// ---------------------------------------------------------------------------
__global__ __launch_bounds__(256)
void softmax_kernel(float* __restrict__ S)
{
    float* row = S + (long long)blockIdx.x * Sq;
    const int tid = threadIdx.x;
    __shared__ float red[256];

    float vals[8];
    float lmax = -INFINITY;
    #pragma unroll
    for (int i = 0; i < 8; i++) {
        vals[i] = row[tid + i * 256];
        lmax = fmaxf(lmax, vals[i]);
    }
    red[tid] = lmax;
    __syncthreads();
    for (int s = 128; s > 0; s >>= 1) {
        if (tid < s) red[tid] = fmaxf(red[tid], red[tid + s]);
        __syncthreads();
    }
    const float m = red[0];
    __syncthreads();

    float lsum = 0.0f;
    #pragma unroll
    for (int i = 0; i < 8; i++) {
        vals[i] = expf(vals[i] - m);
        lsum += vals[i];
    }
    red[tid] = lsum;
    __syncthreads();
    for (int s = 128; s > 0; s >>= 1) {
        if (tid < s) red[tid] += red[tid + s];
        __syncthreads();
    }
    const float inv = 1.0f / red[0];
    #pragma unroll
    for (int i = 0; i < 8; i++) row[tid + i * 256] = rna_tf32(vals[i] * inv);
}

// ---------------------------------------------------------------------------
extern "C" void kernel_launch(void* const* d_in, const int* in_sizes, int n_in,
                              void* d_out, int out_size)
{
    const float* query = (const float*)d_in[0];
    const float* key   = (const float*)d_in[1];
    const float* value = (const float*)d_in[2];
    const float* Wq    = (const float*)d_in[3];
    const float* bq    = (const float*)d_in[4];
    const float* Wk    = (const float*)d_in[5];
    const float* bk    = (const float*)d_in[6];
    const float* Wv    = (const float*)d_in[7];
    const float* bv    = (const float*)d_in[8];
    float* out = (float*)d_out;

    float *pQ, *pK, *pV, *pVt, *pS, *pqr, *pkr, *pvr, *pWqt, *pWkt, *pWvt;
    cudaGetSymbolAddress((void**)&pQ,   g_Q);
    cudaGetSymbolAddress((void**)&pK,   g_K);
    cudaGetSymbolAddress((void**)&pV,   g_V);
    cudaGetSymbolAddress((void**)&pVt,  g_Vt);
    cudaGetSymbolAddress((void**)&pS,   g_S);
    cudaGetSymbolAddress((void**)&pqr,  g_qr);
    cudaGetSymbolAddress((void**)&pkr,  g_kr);
    cudaGetSymbolAddress((void**)&pvr,  g_vr);
    cudaGetSymbolAddress((void**)&pWqt, g_Wqt);
    cudaGetSymbolAddress((void**)&pWkt, g_Wkt);
    cudaGetSymbolAddress((void**)&pWvt, g_Wvt);

    static bool attr_done = false;
    if (!attr_done) {
        cudaFuncSetAttribute(tf32_gemm_nt<true,  true >,
            cudaFuncAttributeMaxDynamicSharedMemorySize, GEMM_SMEM);
        cudaFuncSetAttribute(tf32_gemm_nt<false, false>,
            cudaFuncAttributeMaxDynamicSharedMemorySize, GEMM_SMEM);
        attr_done = true;
    }

    // 0) Pre-round inputs; transpose+round weights
    {
        const int nin = MS * Eq / 4;
        round_tf32_kernel<<<(nin + 255) / 256, 256>>>(query, pqr, nin);
        round_tf32_kernel<<<(nin + 255) / 256, 256>>>(key,   pkr, nin);
        round_tf32_kernel<<<(nin + 255) / 256, 256>>>(value, pvr, nin);
        const dim3 tb(32, 8);
        const dim3 tg(Aq / 32, Eq / 32);
        transpose_round_kernel<<<tg, tb>>>(Wq, pWqt);
        transpose_round_kernel<<<tg, tb>>>(Wk, pWkt);
        transpose_round_kernel<<<tg, tb>>>(Wv, pWvt);
    }

    // 1) Projections (NT vs W^T) + bias, outputs rounded to tf32
    const dim3 gp(Aq / 128, MS / 128, 1);
    tf32_gemm_nt<true, true><<<gp, 128, GEMM_SMEM>>>(pqr, pWqt, bq, pQ, Aq, Eq, 1.0f, 0, 0, 0);
    tf32_gemm_nt<true, true><<<gp, 128, GEMM_SMEM>>>(pkr, pWkt, bk, pK, Aq, Eq, 1.0f, 0, 0, 0);
    tf32_gemm_nt<true, true><<<gp, 128, GEMM_SMEM>>>(pvr, pWvt, bv, pV, Aq, Eq, 1.0f, 0, 0, 0);

    // 1b) V -> V^T per batch
    {
        const dim3 tb(32, 8);
        const dim3 tg(Aq / 32, Sq / 32, Bq);
        transpose_batched_kernel<<<tg, tb>>>(pV, pVt);
    }

    // 2) scores = Q @ K^T / 32 per batch (NT natural: K proj is [S][A])
    const dim3 gs(Sq / 128, Sq / 128, Bq);
    tf32_gemm_nt<false, false><<<gs, 128, GEMM_SMEM>>>(pQ, pK, nullptr, pS,
        Sq, Aq, 1.0f / 32.0f,
        (long long)Sq * Aq, (long long)Sq * Aq, (long long)Sq * Sq);

    // 3) softmax rows (rounds probs to tf32)
    softmax_kernel<<<Bq * Sq, 256>>>(pS);

    // 4) out = P @ (V^T)^T per batch: A = P[2048,2048], B = Vt[1024,2048]
    const dim3 go(Aq / 128, Sq / 128, Bq);
    tf32_gemm_nt<false, false><<<go, 128, GEMM_SMEM>>>(pS, pVt, nullptr, out,
        Aq, Sq, 1.0f,
        (long long)Sq * Sq, (long long)Sq * Aq, (long long)Sq * Aq);
}

// round 6
// speedup vs baseline: 7.0111x; 1.6475x over previous
#include <cuda_runtime.h>
#include <cuda_fp16.h>
#include <math.h>
#include <stdint.h>

// ---------------------------------------------------------------------------
// Attention_80642305950390 — round 6: fp16 mma.sync (m16n8k16, fp32 accum).
// fp16 mantissa == tf32 mantissa (10 bits) -> same error, 2x tensor rate.
// All GEMMs NT, 64x64 warp tile, ldmatrix.b16, 4-stage cp.async ring.
//   B=4, S=2048, E=1024, A=1024.
// ---------------------------------------------------------------------------

#define Bq 4
#define Sq 2048
#define Eq 1024
#define Aq 1024
#define MS (Bq * Sq)

// half scratch
__device__ __half g_qh [(size_t)MS * Eq];
__device__ __half g_kh [(size_t)MS * Eq];
__device__ __half g_vh [(size_t)MS * Eq];
__device__ __half g_Wqt[(size_t)Eq * Aq];    // W^T [A][E], half
__device__ __half g_Wkt[(size_t)Eq * Aq];
__device__ __half g_Wvt[(size_t)Eq * Aq];
__device__ __half g_Qh [(size_t)MS * Aq];    // projections, half
__device__ __half g_Kh [(size_t)MS * Aq];
__device__ __half g_Vh [(size_t)MS * Aq];
__device__ __half g_Vth[(size_t)MS * Aq];    // per-batch V^T [b][A][S]
__device__ __half g_Ph [(size_t)Bq * Sq * Sq]; // probs, half
__device__ float  g_S  [(size_t)Bq * Sq * Sq]; // scores, fp32

// ---------------------------------------------------------------------------
__device__ __forceinline__ uint32_t smem_u32(const void* p) {
    uint32_t a;
    asm("{ .reg .u64 t; cvta.to.shared.u64 t, %1; cvt.u32.u64 %0, t; }"
        : "=r"(a) : "l"(p));
    return a;
}
__device__ __forceinline__ void cp_async16(uint32_t smem, const void* gmem) {
    asm volatile("cp.async.cg.shared.global [%0], [%1], 16;\n" :: "r"(smem), "l"(gmem));
}
#define CP_COMMIT() asm volatile("cp.async.commit_group;\n" ::: "memory")
#define CP_WAIT(N)  asm volatile("cp.async.wait_group %0;\n" :: "n"(N) : "memory")

__device__ __forceinline__ void ldsm_x4(uint32_t addr, uint32_t* r) {
    asm volatile("ldmatrix.sync.aligned.m8n8.x4.shared.b16 {%0,%1,%2,%3}, [%4];"
                 : "=r"(r[0]), "=r"(r[1]), "=r"(r[2]), "=r"(r[3]) : "r"(addr));
}
__device__ __forceinline__ void mma_f16(float* d, const uint32_t* a,
                                        uint32_t b0, uint32_t b1) {
    asm volatile(
        "mma.sync.aligned.m16n8k16.row.col.f32.f16.f16.f32 "
        "{%0,%1,%2,%3},{%4,%5,%6,%7},{%8,%9},{%0,%1,%2,%3};"
        : "+f"(d[0]), "+f"(d[1]), "+f"(d[2]), "+f"(d[3])
        : "r"(a[0]), "r"(a[1]), "r"(a[2]), "r"(a[3]), "r"(b0), "r"(b1));
}

// ---------------------------------------------------------------------------
// NT fp16 GEMM: C[M,N] = alpha * A[M,K] @ B[N,K]^T (+fp32 bias)
// CTA 128x128xBK32(half), 4 warps, warp tile 64x64, 4-stage cp.async ring.
// smem rows: 32 halves (64B) + 16B pad = 80B stride (conflict-free ldmatrix).
// OUT_HALF: store half2 (rn); else fp32. Requires M,N%128==0, K%32==0, K/32>=3.
// ---------------------------------------------------------------------------
#define ROW_B 80
#define AB_PAD_BYTES (128 * ROW_B)            // 10240
#define STAGE_BYTES (2 * AB_PAD_BYTES)        // 20480
#define GEMM_SMEM (4 * STAGE_BYTES)           // 81920

template <bool HASBIAS, bool OUT_HALF>
__global__ __launch_bounds__(128, 2)
void f16_gemm_nt(const __half* __restrict__ A, const __half* __restrict__ B,
                 const float* __restrict__ bias, void* __restrict__ Cv,
                 int N, int K, float alpha,
                 long long sA, long long sB, long long sC)
{
    extern __shared__ char smem[];
    const uint32_t smem_base = smem_u32(smem);

    A += (long long)blockIdx.z * sA;
    B += (long long)blockIdx.z * sB;

    const int tid  = threadIdx.x;
    const int lane = tid & 31;
    const int wid  = tid >> 5;
    const int wm   = wid >> 1;            // 0..1
    const int wn   = wid & 1;             // 0..1
    const int g    = lane >> 2;
    const int t    = lane & 3;
    const int cRow = blockIdx.y * 128;
    const int cCol = blockIdx.x * 128;

    // ldmatrix lane offsets (bytes within stage A/B region)
    const uint32_t a_lane = (uint32_t)((wm * 64 + (lane & 15)) * ROW_B
                                       + (lane >> 4) * 16);
    const uint32_t b_lane = (uint32_t)((wn * 64 + (lane & 7) + ((lane >> 4) & 1) * 8) * ROW_B
                                       + ((lane >> 3) & 1) * 16);

    float acc[4][8][4];
    #pragma unroll
    for (int i = 0; i < 4; i++)
        #pragma unroll
        for (int j = 0; j < 8; j++)
            #pragma unroll
            for (int r = 0; r < 4; r++) acc[i][j][r] = 0.0f;

    const int NK = K >> 5;                // K per tile = 32 halves

    auto load_tile = [&](int stage, int kt) {
        const uint32_t As = smem_base + stage * STAGE_BYTES;
        const uint32_t Bs = As + AB_PAD_BYTES;
        const long long kbase = (long long)(kt << 5);
        #pragma unroll
        for (int i = 0; i < 4; i++) {
            const int ch  = tid + i * 128;      // 0..511
            const int row = ch >> 2;            // 0..127
            const int k4  = ch & 3;             // 16B chunk (8 halves)
            const uint32_t so = (uint32_t)(row * ROW_B + k4 * 16);
            cp_async16(As + so, &A[(long long)(cRow + row) * K + kbase + k4 * 8]);
            cp_async16(Bs + so, &B[(long long)(cCol + row) * K + kbase + k4 * 8]);
        }
    };

    load_tile(0, 0); CP_COMMIT();
    load_tile(1, 1); CP_COMMIT();
    load_tile(2, 2); CP_COMMIT();

    for (int kt = 0; kt < NK; kt++) {
        CP_WAIT(2);
        __syncthreads();

        if (kt + 3 < NK) load_tile((kt + 3) & 3, kt + 3);
        CP_COMMIT();

        const uint32_t sA_base = smem_base + (kt & 3) * STAGE_BYTES + a_lane;
        const uint32_t sB_base = smem_base + (kt & 3) * STAGE_BYTES + AB_PAD_BYTES + b_lane;

        #pragma unroll
        for (int s = 0; s < 2; s++) {
            const uint32_t ko = s * 32;         // k16 halves = 32 bytes
            uint32_t a[4][4], b[4][4];
            #pragma unroll
            for (int mi = 0; mi < 4; mi++)
                ldsm_x4(sA_base + mi * (16 * ROW_B) + ko, a[mi]);
            #pragma unroll
            for (int p = 0; p < 4; p++)
                ldsm_x4(sB_base + p * (16 * ROW_B) + ko, b[p]);
            #pragma unroll
            for (int p = 0; p < 4; p++)
                #pragma unroll
                for (int mi = 0; mi < 4; mi++) {
                    mma_f16(acc[mi][2 * p    ], a[mi], b[p][0], b[p][1]);
                    mma_f16(acc[mi][2 * p + 1], a[mi], b[p][2], b[p][3]);
                }
        }
    }

    // Epilogue
    #pragma unroll
    for (int mi = 0; mi < 4; mi++) {
        const int row0 = cRow + wm * 64 + mi * 16 + g;
        #pragma unroll
        for (int ni = 0; ni < 8; ni++) {
            const int col = cCol + wn * 64 + ni * 8 + t * 2;
            float bx = 0.0f, by = 0.0f;
            if (HASBIAS) {
                const float2 b2 = *reinterpret_cast<const float2*>(&bias[col]);
                bx = b2.x; by = b2.y;
            }
            const float v0x = acc[mi][ni][0] * alpha + bx;
            const float v0y = acc[mi][ni][1] * alpha + by;
            const float v1x = acc[mi][ni][2] * alpha + bx;
            const float v1y = acc[mi][ni][3] * alpha + by;
            if (OUT_HALF) {
                __half* C = (__half*)Cv + (long long)blockIdx.z * sC;
                *reinterpret_cast<__half2*>(&C[(long long)row0 * N + col]) =
                    __floats2half2_rn(v0x, v0y);
                *reinterpret_cast<__half2*>(&C[(long long)(row0 + 8) * N + col]) =
                    __floats2half2_rn(v1x, v1y);
            } else {
                float* C = (float*)Cv + (long long)blockIdx.z * sC;
                float2 a2; a2.x = v0x; a2.y = v0y;
                float2 c2; c2.x = v1x; c2.y = v1y;
                *reinterpret_cast<float2*>(&C[(long long)row0 * N + col]) = a2;
                *reinterpret_cast<float2*>(&C[(long long)(row0 + 8) * N + col]) = c2;
            }
        }
    }
}

// ---------------------------------------------------------------------------
// fp32 -> fp16 convert (float4 -> 2x half2), n4 = count of float4
// ---------------------------------------------------------------------------
__global__ __launch_bounds__(256)
void cvt_half_kernel(const float* __restrict__ in, __half2* __restrict__ out, int n4)
{
    int i = blockIdx.x * blockDim.x + threadIdx.x;
    if (i < n4) {
        float4 v = reinterpret_cast<const float4*>(in)[i];
        out[2 * i    ] = __floats2half2_rn(v.x, v.y);
        out[2 * i + 1] = __floats2half2_rn(v.z, v.w);
    }
}

// ---------------------------------------------------------------------------
// W [E][A] fp32 -> W^T [A][E] half
// ---------------------------------------------------------------------------
__global__ __launch_bounds__(256)
void transpose_cvt_kernel(const float* __restrict__ in, __half* __restrict__ out)
{
    __shared__ __half tbuf[32][33];
    const int tx = threadIdx.x, ty = threadIdx.y;
    const int a0 = blockIdx.x * 32;
    const int e0 = blockIdx.y * 32;
    #pragma unroll
    for (int r = 0; r < 4; r++)
        tbuf[ty + r * 8][tx] = __float2half_rn(
            in[(long long)(e0 + ty + r * 8) * Aq + a0 + tx]);
    __syncthreads();
    #pragma unroll
    for (int r = 0; r < 4; r++)
        out[(long long)(a0 + ty + r * 8) * Eq + e0 + tx] = tbuf[tx][ty + r * 8];
}

// ---------------------------------------------------------------------------
// Batched half transpose: in [B][S][A] -> out [B][A][S]
// ---------------------------------------------------------------------------
__global__ __launch_bounds__(256)
void transpose_batched_h_kernel(const __half* __restrict__ in, __half* __restrict__ out)
{
    __shared__ __half tbuf[32][33];
    const int tx = threadIdx.x, ty = threadIdx.y;
    const int a0 = blockIdx.x * 32;
    const int s0 = blockIdx.y * 32;
    const long long bo = (long long)blockIdx.z * Sq * Aq;
    #pragma unroll
    for (int r = 0; r < 4; r++)
        tbuf[ty + r * 8][tx] = in[bo + (long long)(s0 + ty + r * 8) * Aq + a0 + tx];
    __syncthreads();
    #pragma unroll
    for (int r = 0; r < 4; r++)
        out[bo + (long long)(a0 + ty + r * 8) * Sq + s0 + tx] = tbuf[tx][ty + r * 8];
}

// ---------------------------------------------------------------------------
// Row softmax over 2048 fp32 scores; writes half probs.
// ---------------------------------------------------------------------------
__global__ __launch_bounds__(256)
void softmax_kernel(const float* __restrict__ S, __half* __restrict__ P)
{
    const float* row = S + (long long)blockIdx.x * Sq;
    __half* prow = P + (long long)blockIdx.x * Sq;
    const int tid = threadIdx.x;
    __shared__ float red[256];

    float vals[8];
    float lmax = -INFINITY;
    #pragma unroll
    for (int i = 0; i < 8; i++) {
        vals[i] = row[tid + i * 256];
        lmax = fmaxf(lmax, vals[i]);
    }
    red[tid] = lmax;
    __syncthreads();
    for (int s = 128; s > 0; s >>= 1) {
        if (tid < s) red[tid] = fmaxf(red[tid], red[tid + s]);
        __syncthreads();
    }
    const float m = red[0];
    __syncthreads();

    float lsum = 0.0f;
    #pragma unroll
    for (int i = 0; i < 8; i++) {
        vals[i] = expf(vals[i] - m);
        lsum += vals[i];
    }
    red[tid] = lsum;
    __syncthreads();
    for (int s = 128; s > 0; s >>= 1) {
        if (tid < s) red[tid] += red[tid + s];
        __syncthreads();
    }
    const float inv = 1.0f / red[0];
    #pragma unroll
    for (int i = 0; i < 8; i++)
        prow[tid + i * 256] = __float2half_rn(vals[i] * inv);
}

// ---------------------------------------------------------------------------
extern "C" void kernel_launch(void* const* d_in, const int* in_sizes, int n_in,
                              void* d_out, int out_size)
{
    const float* query = (const float*)d_in[0];
    const float* key   = (const float*)d_in[1];
    const float* value = (const float*)d_in[2];
    const float* Wq    = (const float*)d_in[3];
    const float* bq    = (const float*)d_in[4];
    const float* Wk    = (const float*)d_in[5];
    const float* bk    = (const float*)d_in[6];
    const float* Wv    = (const float*)d_in[7];
    const float* bv    = (const float*)d_in[8];
    float* out = (float*)d_out;

    __half *pqh, *pkh, *pvh, *pWqt, *pWkt, *pWvt, *pQh, *pKh, *pVh, *pVth, *pPh;
    float* pS;
    cudaGetSymbolAddress((void**)&pqh,  g_qh);
    cudaGetSymbolAddress((void**)&pkh,  g_kh);
    cudaGetSymbolAddress((void**)&pvh,  g_vh);
    cudaGetSymbolAddress((void**)&pWqt, g_Wqt);
    cudaGetSymbolAddress((void**)&pWkt, g_Wkt);
    cudaGetSymbolAddress((void**)&pWvt, g_Wvt);
    cudaGetSymbolAddress((void**)&pQh,  g_Qh);
    cudaGetSymbolAddress((void**)&pKh,  g_Kh);
    cudaGetSymbolAddress((void**)&pVh,  g_Vh);
    cudaGetSymbolAddress((void**)&pVth, g_Vth);
    cudaGetSymbolAddress((void**)&pPh,  g_Ph);
    cudaGetSymbolAddress((void**)&pS,   g_S);

    static bool attr_done = false;
    if (!attr_done) {
        cudaFuncSetAttribute(f16_gemm_nt<true,  true >,
            cudaFuncAttributeMaxDynamicSharedMemorySize, GEMM_SMEM);
        cudaFuncSetAttribute(f16_gemm_nt<false, false>,
            cudaFuncAttributeMaxDynamicSharedMemorySize, GEMM_SMEM);
        attr_done = true;
    }

    // 0) Convert inputs to half; transpose+convert weights
    {
        const int nin = MS * Eq / 4;
        cvt_half_kernel<<<(nin + 255) / 256, 256>>>(query, (__half2*)pqh, nin);
        cvt_half_kernel<<<(nin + 255) / 256, 256>>>(key,   (__half2*)pkh, nin);
        cvt_half_kernel<<<(nin + 255) / 256, 256>>>(value, (__half2*)pvh, nin);
        const dim3 tb(32, 8);
        const dim3 tg(Aq / 32, Eq / 32);
        transpose_cvt_kernel<<<tg, tb>>>(Wq, pWqt);
        transpose_cvt_kernel<<<tg, tb>>>(Wk, pWkt);
        transpose_cvt_kernel<<<tg, tb>>>(Wv, pWvt);
    }

    // 1) Projections (NT vs W^T) + bias -> half
    const dim3 gp(Aq / 128, MS / 128, 1);
    f16_gemm_nt<true, true><<<gp, 128, GEMM_SMEM>>>(pqh, pWqt, bq, pQh, Aq, Eq, 1.0f, 0, 0, 0);
    f16_gemm_nt<true, true><<<gp, 128, GEMM_SMEM>>>(pkh, pWkt, bk, pKh, Aq, Eq, 1.0f, 0, 0, 0);
    f16_gemm_nt<true, true><<<gp, 128, GEMM_SMEM>>>(pvh, pWvt, bv, pVh, Aq, Eq, 1.0f, 0, 0, 0);

    // 1b) V -> V^T per batch (half)
    {
        const dim3 tb(32, 8);
        const dim3 tg(Aq / 32, Sq / 32, Bq);
        transpose_batched_h_kernel<<<tg, tb>>>(pVh, pVth);
    }

    // 2) scores = Q @ K^T / 32 per batch -> fp32
    const dim3 gs(Sq / 128, Sq / 128, Bq);
    f16_gemm_nt<false, false><<<gs, 128, GEMM_SMEM>>>(pQh, pKh, nullptr, pS,
        Sq, Aq, 1.0f / 32.0f,
        (long long)Sq * Aq, (long long)Sq * Aq, (long long)Sq * Sq);

    // 3) softmax rows -> half probs
    softmax_kernel<<<Bq * Sq, 256>>>(pS, pPh);

    // 4) out = P @ (V^T)^T per batch -> fp32 d_out
    const dim3 go(Aq / 128, Sq / 128, Bq);
    f16_gemm_nt<false, false><<<go, 128, GEMM_SMEM>>>(pPh, pVth, nullptr, out,
        Aq, Sq, 1.0f,
        (long long)Sq * Sq, (long long)Sq * Aq, (long long)Sq * Aq);
}

// round 8
// speedup vs baseline: 7.0817x; 1.0101x over previous
#include <cuda_runtime.h>
#include <cuda_fp16.h>
#include <math.h>
#include <stdint.h>

// ---------------------------------------------------------------------------
// Attention_80642305950390 — round 8: fp16 mma.sync pipeline, V^T fused into
// the V-projection epilogue (writeback stride bug fixed: 16 x 8-half chunks).
//   B=4, S=2048, E=1024, A=1024.
// ---------------------------------------------------------------------------

#define Bq 4
#define Sq 2048
#define Eq 1024
#define Aq 1024
#define MS (Bq * Sq)

__device__ __half g_qh [(size_t)MS * Eq];
__device__ __half g_kh [(size_t)MS * Eq];
__device__ __half g_vh [(size_t)MS * Eq];
__device__ __half g_Wqt[(size_t)Eq * Aq];
__device__ __half g_Wkt[(size_t)Eq * Aq];
__device__ __half g_Wvt[(size_t)Eq * Aq];
__device__ __half g_Qh [(size_t)MS * Aq];
__device__ __half g_Kh [(size_t)MS * Aq];
__device__ __half g_Vth[(size_t)MS * Aq];      // per-batch V^T [b][A][S]
__device__ __half g_Ph [(size_t)Bq * Sq * Sq];
__device__ float  g_S  [(size_t)Bq * Sq * Sq];

// ---------------------------------------------------------------------------
__device__ __forceinline__ uint32_t smem_u32(const void* p) {
    uint32_t a;
    asm("{ .reg .u64 t; cvta.to.shared.u64 t, %1; cvt.u32.u64 %0, t; }"
        : "=r"(a) : "l"(p));
    return a;
}
__device__ __forceinline__ void cp_async16(uint32_t smem, const void* gmem) {
    asm volatile("cp.async.cg.shared.global [%0], [%1], 16;\n" :: "r"(smem), "l"(gmem));
}
#define CP_COMMIT() asm volatile("cp.async.commit_group;\n" ::: "memory")
#define CP_WAIT(N)  asm volatile("cp.async.wait_group %0;\n" :: "n"(N) : "memory")

__device__ __forceinline__ void ldsm_x4(uint32_t addr, uint32_t* r) {
    asm volatile("ldmatrix.sync.aligned.m8n8.x4.shared.b16 {%0,%1,%2,%3}, [%4];"
                 : "=r"(r[0]), "=r"(r[1]), "=r"(r[2]), "=r"(r[3]) : "r"(addr));
}
__device__ __forceinline__ void mma_f16(float* d, const uint32_t* a,
                                        uint32_t b0, uint32_t b1) {
    asm volatile(
        "mma.sync.aligned.m16n8k16.row.col.f32.f16.f16.f32 "
        "{%0,%1,%2,%3},{%4,%5,%6,%7},{%8,%9},{%0,%1,%2,%3};"
        : "+f"(d[0]), "+f"(d[1]), "+f"(d[2]), "+f"(d[3])
        : "r"(a[0]), "r"(a[1]), "r"(a[2]), "r"(a[3]), "r"(b0), "r"(b1));
}

// ---------------------------------------------------------------------------
// NT fp16 GEMM: C[M,N] = alpha * A[M,K] @ B[N,K]^T (+fp32 bias)
// CTA 128x128xBK32, 4 warps, warp tile 64x64, 4-stage cp.async ring.
// OUT mode: 0 = fp32, 1 = half, 2 = half transposed per batch [b][n][m]
// ---------------------------------------------------------------------------
#define ROW_B 80
#define AB_PAD_BYTES (128 * ROW_B)
#define STAGE_BYTES (2 * AB_PAD_BYTES)
#define GEMM_SMEM (4 * STAGE_BYTES)           // 81920

template <bool HASBIAS, int OUT_MODE>
__global__ __launch_bounds__(128, 2)
void f16_gemm_nt(const __half* __restrict__ A, const __half* __restrict__ B,
                 const float* __restrict__ bias, void* __restrict__ Cv,
                 int N, int K, float alpha,
                 long long sA, long long sB, long long sC)
{
    extern __shared__ char smem[];
    const uint32_t smem_base = smem_u32(smem);

    A += (long long)blockIdx.z * sA;
    B += (long long)blockIdx.z * sB;

    const int tid  = threadIdx.x;
    const int lane = tid & 31;
    const int wid  = tid >> 5;
    const int wm   = wid >> 1;
    const int wn   = wid & 1;
    const int g    = lane >> 2;
    const int t    = lane & 3;
    const int cRow = blockIdx.y * 128;
    const int cCol = blockIdx.x * 128;

    const uint32_t a_lane = (uint32_t)((wm * 64 + (lane & 15)) * ROW_B
                                       + (lane >> 4) * 16);
    const uint32_t b_lane = (uint32_t)((wn * 64 + (lane & 7) + ((lane >> 4) & 1) * 8) * ROW_B
                                       + ((lane >> 3) & 1) * 16);

    float acc[4][8][4];
    #pragma unroll
    for (int i = 0; i < 4; i++)
        #pragma unroll
        for (int j = 0; j < 8; j++)
            #pragma unroll
            for (int r = 0; r < 4; r++) acc[i][j][r] = 0.0f;

    const int NK = K >> 5;

    auto load_tile = [&](int stage, int kt) {
        const uint32_t As = smem_base + stage * STAGE_BYTES;
        const uint32_t Bs = As + AB_PAD_BYTES;
        const long long kbase = (long long)(kt << 5);
        #pragma unroll
        for (int i = 0; i < 4; i++) {
            const int ch  = tid + i * 128;
            const int row = ch >> 2;
            const int k4  = ch & 3;
            const uint32_t so = (uint32_t)(row * ROW_B + k4 * 16);
            cp_async16(As + so, &A[(long long)(cRow + row) * K + kbase + k4 * 8]);
            cp_async16(Bs + so, &B[(long long)(cCol + row) * K + kbase + k4 * 8]);
        }
    };

    load_tile(0, 0); CP_COMMIT();
    load_tile(1, 1); CP_COMMIT();
    load_tile(2, 2); CP_COMMIT();

    for (int kt = 0; kt < NK; kt++) {
        CP_WAIT(2);
        __syncthreads();

        if (kt + 3 < NK) load_tile((kt + 3) & 3, kt + 3);
        CP_COMMIT();

        const uint32_t sA_base = smem_base + (kt & 3) * STAGE_BYTES + a_lane;
        const uint32_t sB_base = smem_base + (kt & 3) * STAGE_BYTES + AB_PAD_BYTES + b_lane;

        #pragma unroll
        for (int s = 0; s < 2; s++) {
            const uint32_t ko = s * 32;
            uint32_t a[4][4], b[4][4];
            #pragma unroll
            for (int mi = 0; mi < 4; mi++)
                ldsm_x4(sA_base + mi * (16 * ROW_B) + ko, a[mi]);
            #pragma unroll
            for (int p = 0; p < 4; p++)
                ldsm_x4(sB_base + p * (16 * ROW_B) + ko, b[p]);
            #pragma unroll
            for (int p = 0; p < 4; p++)
                #pragma unroll
                for (int mi = 0; mi < 4; mi++) {
                    mma_f16(acc[mi][2 * p    ], a[mi], b[p][0], b[p][1]);
                    mma_f16(acc[mi][2 * p + 1], a[mi], b[p][2], b[p][3]);
                }
        }
    }

    if (OUT_MODE != 2) {
        #pragma unroll
        for (int mi = 0; mi < 4; mi++) {
            const int row0 = cRow + wm * 64 + mi * 16 + g;
            #pragma unroll
            for (int ni = 0; ni < 8; ni++) {
                const int col = cCol + wn * 64 + ni * 8 + t * 2;
                float bx = 0.0f, by = 0.0f;
                if (HASBIAS) {
                    const float2 b2 = *reinterpret_cast<const float2*>(&bias[col]);
                    bx = b2.x; by = b2.y;
                }
                const float v0x = acc[mi][ni][0] * alpha + bx;
                const float v0y = acc[mi][ni][1] * alpha + by;
                const float v1x = acc[mi][ni][2] * alpha + bx;
                const float v1y = acc[mi][ni][3] * alpha + by;
                if (OUT_MODE == 1) {
                    __half* C = (__half*)Cv + (long long)blockIdx.z * sC;
                    *reinterpret_cast<__half2*>(&C[(long long)row0 * N + col]) =
                        __floats2half2_rn(v0x, v0y);
                    *reinterpret_cast<__half2*>(&C[(long long)(row0 + 8) * N + col]) =
                        __floats2half2_rn(v1x, v1y);
                } else {
                    float* C = (float*)Cv + (long long)blockIdx.z * sC;
                    float2 a2; a2.x = v0x; a2.y = v0y;
                    float2 c2; c2.x = v1x; c2.y = v1y;
                    *reinterpret_cast<float2*>(&C[(long long)row0 * N + col]) = a2;
                    *reinterpret_cast<float2*>(&C[(long long)(row0 + 8) * N + col]) = c2;
                }
            }
        }
    } else {
        // Transposed half store: stage tile in smem as [n_local][m_local].
        __syncthreads();   // mainloop smem no longer needed
        __half* sT = reinterpret_cast<__half*>(smem);
        const int TP = 136;                     // padded m-stride (halves)
        #pragma unroll
        for (int mi = 0; mi < 4; mi++) {
            const int ml0 = wm * 64 + mi * 16 + g;
            #pragma unroll
            for (int ni = 0; ni < 8; ni++) {
                const int nl = wn * 64 + ni * 8 + t * 2;
                float bx = 0.0f, by = 0.0f;
                if (HASBIAS) {
                    const float2 b2 = *reinterpret_cast<const float2*>(&bias[cCol + nl]);
                    bx = b2.x; by = b2.y;
                }
                sT[(nl    ) * TP + ml0    ] = __float2half_rn(acc[mi][ni][0] * alpha + bx);
                sT[(nl + 1) * TP + ml0    ] = __float2half_rn(acc[mi][ni][1] * alpha + by);
                sT[(nl    ) * TP + ml0 + 8] = __float2half_rn(acc[mi][ni][2] * alpha + bx);
                sT[(nl + 1) * TP + ml0 + 8] = __float2half_rn(acc[mi][ni][3] * alpha + by);
            }
        }
        __syncthreads();
        __half* C = (__half*)Cv;
        const int b    = cRow / Sq;
        const int mloc = cRow % Sq;
        // 128 n-rows x 128 m-halves, 8 halves (16B) per store:
        // 2048 chunks / 128 threads = 16 iterations.
        #pragma unroll
        for (int i = 0; i < 16; i++) {
            const int idx = tid + i * 128;      // 0..2047
            const int nl  = idx >> 4;           // 0..127
            const int m8  = (idx & 15) * 8;     // 8-half chunk
            const long long co = ((long long)b * Aq + cCol + nl) * Sq + mloc + m8;
            float4 v = *reinterpret_cast<const float4*>(&sT[nl * TP + m8]);
            *reinterpret_cast<float4*>(&C[co]) = v;
        }
    }
}

// ---------------------------------------------------------------------------
__global__ __launch_bounds__(256)
void cvt_half_kernel(const float* __restrict__ in, __half2* __restrict__ out, int n4)
{
    int i = blockIdx.x * blockDim.x + threadIdx.x;
    if (i < n4) {
        float4 v = reinterpret_cast<const float4*>(in)[i];
        out[2 * i    ] = __floats2half2_rn(v.x, v.y);
        out[2 * i + 1] = __floats2half2_rn(v.z, v.w);
    }
}

__global__ __launch_bounds__(256)
void transpose_cvt_kernel(const float* __restrict__ in, __half* __restrict__ out)
{
    __shared__ __half tbuf[32][33];
    const int tx = threadIdx.x, ty = threadIdx.y;
    const int a0 = blockIdx.x * 32;
    const int e0 = blockIdx.y * 32;
    #pragma unroll
    for (int r = 0; r < 4; r++)
        tbuf[ty + r * 8][tx] = __float2half_rn(
            in[(long long)(e0 + ty + r * 8) * Aq + a0 + tx]);
    __syncthreads();
    #pragma unroll
    for (int r = 0; r < 4; r++)
        out[(long long)(a0 + ty + r * 8) * Eq + e0 + tx] = tbuf[tx][ty + r * 8];
}

// ---------------------------------------------------------------------------
__global__ __launch_bounds__(256)
void softmax_kernel(const float* __restrict__ S, __half* __restrict__ P)
{
    const float* row = S + (long long)blockIdx.x * Sq;
    __half* prow = P + (long long)blockIdx.x * Sq;
    const int tid = threadIdx.x;
    __shared__ float red[256];

    float vals[8];
    float lmax = -INFINITY;
    #pragma unroll
    for (int i = 0; i < 8; i++) {
        vals[i] = row[tid + i * 256];
        lmax = fmaxf(lmax, vals[i]);
    }
    red[tid] = lmax;
    __syncthreads();
    for (int s = 128; s > 0; s >>= 1) {
        if (tid < s) red[tid] = fmaxf(red[tid], red[tid + s]);
        __syncthreads();
    }
    const float m = red[0];
    __syncthreads();

    float lsum = 0.0f;
    #pragma unroll
    for (int i = 0; i < 8; i++) {
        vals[i] = expf(vals[i] - m);
        lsum += vals[i];
    }
    red[tid] = lsum;
    __syncthreads();
    for (int s = 128; s > 0; s >>= 1) {
        if (tid < s) red[tid] += red[tid + s];
        __syncthreads();
    }
    const float inv = 1.0f / red[0];
    #pragma unroll
    for (int i = 0; i < 8; i++)
        prow[tid + i * 256] = __float2half_rn(vals[i] * inv);
}

// ---------------------------------------------------------------------------
extern "C" void kernel_launch(void* const* d_in, const int* in_sizes, int n_in,
                              void* d_out, int out_size)
{
    const float* query = (const float*)d_in[0];
    const float* key   = (const float*)d_in[1];
    const float* value = (const float*)d_in[2];
    const float* Wq    = (const float*)d_in[3];
    const float* bq    = (const float*)d_in[4];
    const float* Wk    = (const float*)d_in[5];
    const float* bk    = (const float*)d_in[6];
    const float* Wv    = (const float*)d_in[7];
    const float* bv    = (const float*)d_in[8];
    float* out = (float*)d_out;

    __half *pqh, *pkh, *pvh, *pWqt, *pWkt, *pWvt, *pQh, *pKh, *pVth, *pPh;
    float* pS;
    cudaGetSymbolAddress((void**)&pqh,  g_qh);
    cudaGetSymbolAddress((void**)&pkh,  g_kh);
    cudaGetSymbolAddress((void**)&pvh,  g_vh);
    cudaGetSymbolAddress((void**)&pWqt, g_Wqt);
    cudaGetSymbolAddress((void**)&pWkt, g_Wkt);
    cudaGetSymbolAddress((void**)&pWvt, g_Wvt);
    cudaGetSymbolAddress((void**)&pQh,  g_Qh);
    cudaGetSymbolAddress((void**)&pKh,  g_Kh);
    cudaGetSymbolAddress((void**)&pVth, g_Vth);
    cudaGetSymbolAddress((void**)&pPh,  g_Ph);
    cudaGetSymbolAddress((void**)&pS,   g_S);

    static bool attr_done = false;
    if (!attr_done) {
        cudaFuncSetAttribute(f16_gemm_nt<true,  1>,
            cudaFuncAttributeMaxDynamicSharedMemorySize, GEMM_SMEM);
        cudaFuncSetAttribute(f16_gemm_nt<true,  2>,
            cudaFuncAttributeMaxDynamicSharedMemorySize, GEMM_SMEM);
        cudaFuncSetAttribute(f16_gemm_nt<false, 0>,
            cudaFuncAttributeMaxDynamicSharedMemorySize, GEMM_SMEM);
        attr_done = true;
    }

    const int nin = MS * Eq / 4;
    const dim3 tb(32, 8);
    const dim3 tg(Aq / 32, Eq / 32);
    const dim3 gp(Aq / 128, MS / 128, 1);

    // Launch order puts a projection GEMM at index 5 for ncu (-s 5 -c 1).
    cvt_half_kernel<<<(nin + 255) / 256, 256>>>(query, (__half2*)pqh, nin);   // 0
    cvt_half_kernel<<<(nin + 255) / 256, 256>>>(key,   (__half2*)pkh, nin);   // 1
    cvt_half_kernel<<<(nin + 255) / 256, 256>>>(value, (__half2*)pvh, nin);   // 2
    transpose_cvt_kernel<<<tg, tb>>>(Wq, pWqt);                               // 3
    transpose_cvt_kernel<<<tg, tb>>>(Wk, pWkt);                               // 4
    f16_gemm_nt<true, 1><<<gp, 128, GEMM_SMEM>>>(pqh, pWqt, bq, pQh,          // 5 (ncu)
        Aq, Eq, 1.0f, 0, 0, 0);
    transpose_cvt_kernel<<<tg, tb>>>(Wv, pWvt);                               // 6
    f16_gemm_nt<true, 1><<<gp, 128, GEMM_SMEM>>>(pkh, pWkt, bk, pKh,          // 7
        Aq, Eq, 1.0f, 0, 0, 0);
    f16_gemm_nt<true, 2><<<gp, 128, GEMM_SMEM>>>(pvh, pWvt, bv, pVth,         // 8: V^T fused
        Aq, Eq, 1.0f, 0, 0, 0);

    const dim3 gs(Sq / 128, Sq / 128, Bq);
    f16_gemm_nt<false, 0><<<gs, 128, GEMM_SMEM>>>(pQh, pKh, nullptr, pS,      // 9
        Sq, Aq, 1.0f / 32.0f,
        (long long)Sq * Aq, (long long)Sq * Aq, (long long)Sq * Sq);

    softmax_kernel<<<Bq * Sq, 256>>>(pS, pPh);                                // 10

    const dim3 go(Aq / 128, Sq / 128, Bq);
    f16_gemm_nt<false, 0><<<go, 128, GEMM_SMEM>>>(pPh, pVth, nullptr, out,    // 11
        Aq, Sq, 1.0f,
        (long long)Sq * Sq, (long long)Sq * Aq, (long long)Sq * Aq);
}

// round 10
// speedup vs baseline: 7.8115x; 1.1031x over previous
#include <cuda_runtime.h>
#include <cuda_fp16.h>
#include <math.h>
#include <stdint.h>

// ---------------------------------------------------------------------------
// Attention_80642305950390 — round 10: single-stream, merged launches.
//   cvt(z=3) -> Wtranspose(z=3) -> QKV projection (one grid, z=3, V^T fused)
//   -> scores(z=4) -> shuffle softmax -> PV(z=4).
// GEMM core identical to round 8 (fp16 mma.sync, 64x64 warp tile, 4-stage).
//   B=4, S=2048, E=1024, A=1024.
// ---------------------------------------------------------------------------

#define Bq 4
#define Sq 2048
#define Eq 1024
#define Aq 1024
#define MS (Bq * Sq)

__device__ __half g_qh [(size_t)MS * Eq];
__device__ __half g_kh [(size_t)MS * Eq];
__device__ __half g_vh [(size_t)MS * Eq];
__device__ __half g_Wqt[(size_t)Eq * Aq];
__device__ __half g_Wkt[(size_t)Eq * Aq];
__device__ __half g_Wvt[(size_t)Eq * Aq];
__device__ __half g_Qh [(size_t)MS * Aq];
__device__ __half g_Kh [(size_t)MS * Aq];
__device__ __half g_Vth[(size_t)MS * Aq];      // per-batch V^T [b][A][S]
__device__ __half g_Ph [(size_t)Bq * Sq * Sq];
__device__ float  g_S  [(size_t)Bq * Sq * Sq];

// ---------------------------------------------------------------------------
__device__ __forceinline__ uint32_t smem_u32(const void* p) {
    uint32_t a;
    asm("{ .reg .u64 t; cvta.to.shared.u64 t, %1; cvt.u32.u64 %0, t; }"
        : "=r"(a) : "l"(p));
    return a;
}
__device__ __forceinline__ void cp_async16(uint32_t smem, const void* gmem) {
    asm volatile("cp.async.cg.shared.global [%0], [%1], 16;\n" :: "r"(smem), "l"(gmem));
}
#define CP_COMMIT() asm volatile("cp.async.commit_group;\n" ::: "memory")
#define CP_WAIT(N)  asm volatile("cp.async.wait_group %0;\n" :: "n"(N) : "memory")

__device__ __forceinline__ void ldsm_x4(uint32_t addr, uint32_t* r) {
    asm volatile("ldmatrix.sync.aligned.m8n8.x4.shared.b16 {%0,%1,%2,%3}, [%4];"
                 : "=r"(r[0]), "=r"(r[1]), "=r"(r[2]), "=r"(r[3]) : "r"(addr));
}
__device__ __forceinline__ void mma_f16(float* d, const uint32_t* a,
                                        uint32_t b0, uint32_t b1) {
    asm volatile(
        "mma.sync.aligned.m16n8k16.row.col.f32.f16.f16.f32 "
        "{%0,%1,%2,%3},{%4,%5,%6,%7},{%8,%9},{%0,%1,%2,%3};"
        : "+f"(d[0]), "+f"(d[1]), "+f"(d[2]), "+f"(d[3])
        : "r"(a[0]), "r"(a[1]), "r"(a[2]), "r"(a[3]), "r"(b0), "r"(b1));
}

#define ROW_B 80
#define AB_PAD_BYTES (128 * ROW_B)
#define STAGE_BYTES (2 * AB_PAD_BYTES)
#define GEMM_SMEM (4 * STAGE_BYTES)           // 81920

// ---------------------------------------------------------------------------
// Shared mainloop: accumulates 128x128 tile of A[M,K] @ B[N,K]^T.
// ---------------------------------------------------------------------------
struct GemmCtx {
    float acc[4][8][4];
};

__device__ __forceinline__ void gemm_mainloop(
    GemmCtx& ctx, const __half* __restrict__ A, const __half* __restrict__ B,
    int K, int cRow, int cCol, uint32_t smem_base,
    int tid, uint32_t a_lane, uint32_t b_lane)
{
    #pragma unroll
    for (int i = 0; i < 4; i++)
        #pragma unroll
        for (int j = 0; j < 8; j++)
            #pragma unroll
            for (int r = 0; r < 4; r++) ctx.acc[i][j][r] = 0.0f;

    const int NK = K >> 5;

    auto load_tile = [&](int stage, int kt) {
        const uint32_t As = smem_base + stage * STAGE_BYTES;
        const uint32_t Bs = As + AB_PAD_BYTES;
        const long long kbase = (long long)(kt << 5);
        #pragma unroll
        for (int i = 0; i < 4; i++) {
            const int ch  = tid + i * 128;
            const int row = ch >> 2;
            const int k4  = ch & 3;
            const uint32_t so = (uint32_t)(row * ROW_B + k4 * 16);
            cp_async16(As + so, &A[(long long)(cRow + row) * K + kbase + k4 * 8]);
            cp_async16(Bs + so, &B[(long long)(cCol + row) * K + kbase + k4 * 8]);
        }
    };

    load_tile(0, 0); CP_COMMIT();
    load_tile(1, 1); CP_COMMIT();
    load_tile(2, 2); CP_COMMIT();

    for (int kt = 0; kt < NK; kt++) {
        CP_WAIT(2);
        __syncthreads();

        if (kt + 3 < NK) load_tile((kt + 3) & 3, kt + 3);
        CP_COMMIT();

        const uint32_t sA_base = smem_base + (kt & 3) * STAGE_BYTES + a_lane;
        const uint32_t sB_base = smem_base + (kt & 3) * STAGE_BYTES + AB_PAD_BYTES + b_lane;

        #pragma unroll
        for (int s = 0; s < 2; s++) {
            const uint32_t ko = s * 32;
            uint32_t a[4][4], b[4][4];
            #pragma unroll
            for (int mi = 0; mi < 4; mi++)
                ldsm_x4(sA_base + mi * (16 * ROW_B) + ko, a[mi]);
            #pragma unroll
            for (int p = 0; p < 4; p++)
                ldsm_x4(sB_base + p * (16 * ROW_B) + ko, b[p]);
            #pragma unroll
            for (int p = 0; p < 4; p++)
                #pragma unroll
                for (int mi = 0; mi < 4; mi++) {
                    mma_f16(ctx.acc[mi][2 * p    ], a[mi], b[p][0], b[p][1]);
                    mma_f16(ctx.acc[mi][2 * p + 1], a[mi], b[p][2], b[p][3]);
                }
        }
    }
}

// ---------------------------------------------------------------------------
// Merged QKV projection: grid (8, 64, 3). z: 0=Q, 1=K (half out), 2=V (half
// transposed out per batch [b][A][S]). M=8192, N=A=1024, K=E=1024, bias.
// ---------------------------------------------------------------------------
__global__ __launch_bounds__(128, 2)
void qkv_proj_kernel(const __half* __restrict__ qh, const __half* __restrict__ kh,
                     const __half* __restrict__ vh,
                     const __half* __restrict__ Wqt, const __half* __restrict__ Wkt,
                     const __half* __restrict__ Wvt,
                     const float* __restrict__ bq, const float* __restrict__ bk,
                     const float* __restrict__ bv,
                     __half* __restrict__ Qh, __half* __restrict__ Kh,
                     __half* __restrict__ Vth)
{
    extern __shared__ char smem[];
    const uint32_t smem_base = smem_u32(smem);
    const int z = blockIdx.z;

    const __half* A = (z == 0) ? qh : (z == 1) ? kh : vh;
    const __half* B = (z == 0) ? Wqt : (z == 1) ? Wkt : Wvt;
    const float* bias = (z == 0) ? bq : (z == 1) ? bk : bv;

    const int tid  = threadIdx.x;
    const int lane = tid & 31;
    const int wid  = tid >> 5;
    const int wm   = wid >> 1;
    const int wn   = wid & 1;
    const int g    = lane >> 2;
    const int t    = lane & 3;
    const int cRow = blockIdx.y * 128;
    const int cCol = blockIdx.x * 128;

    const uint32_t a_lane = (uint32_t)((wm * 64 + (lane & 15)) * ROW_B
                                       + (lane >> 4) * 16);
    const uint32_t b_lane = (uint32_t)((wn * 64 + (lane & 7) + ((lane >> 4) & 1) * 8) * ROW_B
                                       + ((lane >> 3) & 1) * 16);

    GemmCtx ctx;
    gemm_mainloop(ctx, A, B, Eq, cRow, cCol, smem_base, tid, a_lane, b_lane);

    if (z != 2) {
        __half* C = (z == 0) ? Qh : Kh;
        #pragma unroll
        for (int mi = 0; mi < 4; mi++) {
            const int row0 = cRow + wm * 64 + mi * 16 + g;
            #pragma unroll
            for (int ni = 0; ni < 8; ni++) {
                const int col = cCol + wn * 64 + ni * 8 + t * 2;
                const float2 b2 = *reinterpret_cast<const float2*>(&bias[col]);
                *reinterpret_cast<__half2*>(&C[(long long)row0 * Aq + col]) =
                    __floats2half2_rn(ctx.acc[mi][ni][0] + b2.x,
                                      ctx.acc[mi][ni][1] + b2.y);
                *reinterpret_cast<__half2*>(&C[(long long)(row0 + 8) * Aq + col]) =
                    __floats2half2_rn(ctx.acc[mi][ni][2] + b2.x,
                                      ctx.acc[mi][ni][3] + b2.y);
            }
        }
    } else {
        // Transposed half store via smem staging [n_local][m_local].
        __syncthreads();
        __half* sT = reinterpret_cast<__half*>(smem);
        const int TP = 136;
        #pragma unroll
        for (int mi = 0; mi < 4; mi++) {
            const int ml0 = wm * 64 + mi * 16 + g;
            #pragma unroll
            for (int ni = 0; ni < 8; ni++) {
                const int nl = wn * 64 + ni * 8 + t * 2;
                const float2 b2 = *reinterpret_cast<const float2*>(&bias[cCol + nl]);
                sT[(nl    ) * TP + ml0    ] = __float2half_rn(ctx.acc[mi][ni][0] + b2.x);
                sT[(nl + 1) * TP + ml0    ] = __float2half_rn(ctx.acc[mi][ni][1] + b2.y);
                sT[(nl    ) * TP + ml0 + 8] = __float2half_rn(ctx.acc[mi][ni][2] + b2.x);
                sT[(nl + 1) * TP + ml0 + 8] = __float2half_rn(ctx.acc[mi][ni][3] + b2.y);
            }
        }
        __syncthreads();
        const int b    = cRow / Sq;
        const int mloc = cRow % Sq;
        #pragma unroll
        for (int i = 0; i < 16; i++) {
            const int idx = tid + i * 128;
            const int nl  = idx >> 4;
            const int m8  = (idx & 15) * 8;
            const long long co = ((long long)b * Aq + cCol + nl) * Sq + mloc + m8;
            float4 v = *reinterpret_cast<const float4*>(&sT[nl * TP + m8]);
            *reinterpret_cast<float4*>(&Vth[co]) = v;
        }
    }
}

// ---------------------------------------------------------------------------
// Attention GEMMs (NT, no bias): OUT fp32 (scores) or fp32 to d_out (PV).
// ---------------------------------------------------------------------------
__global__ __launch_bounds__(128, 2)
void attn_gemm_kernel(const __half* __restrict__ A, const __half* __restrict__ B,
                      float* __restrict__ C, int N, int K, float alpha,
                      long long sA, long long sB, long long sC)
{
    extern __shared__ char smem[];
    const uint32_t smem_base = smem_u32(smem);

    A += (long long)blockIdx.z * sA;
    B += (long long)blockIdx.z * sB;
    C += (long long)blockIdx.z * sC;

    const int tid  = threadIdx.x;
    const int lane = tid & 31;
    const int wid  = tid >> 5;
    const int wm   = wid >> 1;
    const int wn   = wid & 1;
    const int g    = lane >> 2;
    const int t    = lane & 3;
    const int cRow = blockIdx.y * 128;
    const int cCol = blockIdx.x * 128;

    const uint32_t a_lane = (uint32_t)((wm * 64 + (lane & 15)) * ROW_B
                                       + (lane >> 4) * 16);
    const uint32_t b_lane = (uint32_t)((wn * 64 + (lane & 7) + ((lane >> 4) & 1) * 8) * ROW_B
                                       + ((lane >> 3) & 1) * 16);

    GemmCtx ctx;
    gemm_mainloop(ctx, A, B, K, cRow, cCol, smem_base, tid, a_lane, b_lane);

    #pragma unroll
    for (int mi = 0; mi < 4; mi++) {
        const int row0 = cRow + wm * 64 + mi * 16 + g;
        #pragma unroll
        for (int ni = 0; ni < 8; ni++) {
            const int col = cCol + wn * 64 + ni * 8 + t * 2;
            float2 v0, v1;
            v0.x = ctx.acc[mi][ni][0] * alpha;
            v0.y = ctx.acc[mi][ni][1] * alpha;
            v1.x = ctx.acc[mi][ni][2] * alpha;
            v1.y = ctx.acc[mi][ni][3] * alpha;
            *reinterpret_cast<float2*>(&C[(long long)row0 * N + col]) = v0;
            *reinterpret_cast<float2*>(&C[(long long)(row0 + 8) * N + col]) = v1;
        }
    }
}

// ---------------------------------------------------------------------------
// Merged input conversion: grid (nin/256, 1, 3); z selects tensor.
// ---------------------------------------------------------------------------
__global__ __launch_bounds__(256)
void cvt3_kernel(const float* __restrict__ in0, const float* __restrict__ in1,
                 const float* __restrict__ in2,
                 __half2* __restrict__ o0, __half2* __restrict__ o1,
                 __half2* __restrict__ o2, int n4)
{
    const int z = blockIdx.z;
    const float* in = (z == 0) ? in0 : (z == 1) ? in1 : in2;
    __half2* out = (z == 0) ? o0 : (z == 1) ? o1 : o2;
    int i = blockIdx.x * blockDim.x + threadIdx.x;
    if (i < n4) {
        float4 v = reinterpret_cast<const float4*>(in)[i];
        out[2 * i    ] = __floats2half2_rn(v.x, v.y);
        out[2 * i + 1] = __floats2half2_rn(v.z, v.w);
    }
}

// ---------------------------------------------------------------------------
// Merged W transpose+cvt: grid (32, 32, 3).
// ---------------------------------------------------------------------------
__global__ __launch_bounds__(256)
void transpose3_kernel(const float* __restrict__ w0, const float* __restrict__ w1,
                       const float* __restrict__ w2,
                       __half* __restrict__ o0, __half* __restrict__ o1,
                       __half* __restrict__ o2)
{
    const int z = blockIdx.z;
    const float* in = (z == 0) ? w0 : (z == 1) ? w1 : w2;
    __half* out = (z == 0) ? o0 : (z == 1) ? o1 : o2;
    __shared__ __half tbuf[32][33];
    const int tx = threadIdx.x, ty = threadIdx.y;
    const int a0 = blockIdx.x * 32;
    const int e0 = blockIdx.y * 32;
    #pragma unroll
    for (int r = 0; r < 4; r++)
        tbuf[ty + r * 8][tx] = __float2half_rn(
            in[(long long)(e0 + ty + r * 8) * Aq + a0 + tx]);
    __syncthreads();
    #pragma unroll
    for (int r = 0; r < 4; r++)
        out[(long long)(a0 + ty + r * 8) * Eq + e0 + tx] = tbuf[tx][ty + r * 8];
}

// ---------------------------------------------------------------------------
// Row softmax (2048 cols), warp-shuffle reductions.
// ---------------------------------------------------------------------------
__global__ __launch_bounds__(256)
void softmax_kernel(const float* __restrict__ S, __half* __restrict__ P)
{
    const float* row = S + (long long)blockIdx.x * Sq;
    __half* prow = P + (long long)blockIdx.x * Sq;
    const int tid  = threadIdx.x;
    const int lane = tid & 31;
    const int wid  = tid >> 5;
    __shared__ float rmax[8];
    __shared__ float rsum[8];

    float vals[8];
    float lmax = -INFINITY;
    #pragma unroll
    for (int i = 0; i < 8; i++) {
        vals[i] = row[tid + i * 256];
        lmax = fmaxf(lmax, vals[i]);
    }
    #pragma unroll
    for (int o = 16; o > 0; o >>= 1)
        lmax = fmaxf(lmax, __shfl_xor_sync(0xffffffffu, lmax, o));
    if (lane == 0) rmax[wid] = lmax;
    __syncthreads();
    if (tid < 32) {
        float m = (lane < 8) ? rmax[lane] : -INFINITY;
        #pragma unroll
        for (int o = 4; o > 0; o >>= 1)
            m = fmaxf(m, __shfl_xor_sync(0xffffffffu, m, o));
        if (lane == 0) rmax[0] = m;
    }
    __syncthreads();
    const float m = rmax[0];

    float lsum = 0.0f;
    #pragma unroll
    for (int i = 0; i < 8; i++) {
        vals[i] = expf(vals[i] - m);
        lsum += vals[i];
    }
    #pragma unroll
    for (int o = 16; o > 0; o >>= 1)
        lsum += __shfl_xor_sync(0xffffffffu, lsum, o);
    if (lane == 0) rsum[wid] = lsum;
    __syncthreads();
    if (tid < 32) {
        float s = (lane < 8) ? rsum[lane] : 0.0f;
        #pragma unroll
        for (int o = 4; o > 0; o >>= 1)
            s += __shfl_xor_sync(0xffffffffu, s, o);
        if (lane == 0) rsum[0] = s;
    }
    __syncthreads();
    const float inv = 1.0f / rsum[0];
    #pragma unroll
    for (int i = 0; i < 8; i++)
        prow[tid + i * 256] = __float2half_rn(vals[i] * inv);
}

// ---------------------------------------------------------------------------
extern "C" void kernel_launch(void* const* d_in, const int* in_sizes, int n_in,
                              void* d_out, int out_size)
{
    const float* query = (const float*)d_in[0];
    const float* key   = (const float*)d_in[1];
    const float* value = (const float*)d_in[2];
    const float* Wq    = (const float*)d_in[3];
    const float* bq    = (const float*)d_in[4];
    const float* Wk    = (const float*)d_in[5];
    const float* bk    = (const float*)d_in[6];
    const float* Wv    = (const float*)d_in[7];
    const float* bv    = (const float*)d_in[8];
    float* out = (float*)d_out;

    __half *pqh, *pkh, *pvh, *pWqt, *pWkt, *pWvt, *pQh, *pKh, *pVth, *pPh;
    float* pS;
    cudaGetSymbolAddress((void**)&pqh,  g_qh);
    cudaGetSymbolAddress((void**)&pkh,  g_kh);
    cudaGetSymbolAddress((void**)&pvh,  g_vh);
    cudaGetSymbolAddress((void**)&pWqt, g_Wqt);
    cudaGetSymbolAddress((void**)&pWkt, g_Wkt);
    cudaGetSymbolAddress((void**)&pWvt, g_Wvt);
    cudaGetSymbolAddress((void**)&pQh,  g_Qh);
    cudaGetSymbolAddress((void**)&pKh,  g_Kh);
    cudaGetSymbolAddress((void**)&pVth, g_Vth);
    cudaGetSymbolAddress((void**)&pPh,  g_Ph);
    cudaGetSymbolAddress((void**)&pS,   g_S);

    static bool attr_done = false;
    if (!attr_done) {
        cudaFuncSetAttribute(qkv_proj_kernel,
            cudaFuncAttributeMaxDynamicSharedMemorySize, GEMM_SMEM);
        cudaFuncSetAttribute(attn_gemm_kernel,
            cudaFuncAttributeMaxDynamicSharedMemorySize, GEMM_SMEM);
        attr_done = true;
    }

    const int nin = MS * Eq / 4;

    // 1) input conversions (one grid, z=3)
    cvt3_kernel<<<dim3((nin + 255) / 256, 1, 3), 256>>>(
        query, key, value, (__half2*)pqh, (__half2*)pkh, (__half2*)pvh, nin);

    // 2) weight transposes (one grid, z=3)
    transpose3_kernel<<<dim3(Aq / 32, Eq / 32, 3), dim3(32, 8)>>>(
        Wq, Wk, Wv, pWqt, pWkt, pWvt);

    // 3) QKV projections (one grid, z=3; V^T fused)
    qkv_proj_kernel<<<dim3(Aq / 128, MS / 128, 3), 128, GEMM_SMEM>>>(
        pqh, pkh, pvh, pWqt, pWkt, pWvt, bq, bk, bv, pQh, pKh, pVth);

    // 4) scores = Q @ K^T / 32 (batched z=4)
    attn_gemm_kernel<<<dim3(Sq / 128, Sq / 128, Bq), 128, GEMM_SMEM>>>(
        pQh, pKh, pS, Sq, Aq, 1.0f / 32.0f,
        (long long)Sq * Aq, (long long)Sq * Aq, (long long)Sq * Sq);

    // 5) softmax -> half probs
    softmax_kernel<<<Bq * Sq, 256>>>(pS, pPh);

    // 6) out = P @ (V^T)^T (batched z=4) -> d_out fp32
    attn_gemm_kernel<<<dim3(Aq / 128, Sq / 128, Bq), 128, GEMM_SMEM>>>(
        pPh, pVth, out, Aq, Sq, 1.0f,
        (long long)Sq * Sq, (long long)Sq * Aq, (long long)Sq * Aq);
}

// round 11
// speedup vs baseline: 7.9557x; 1.0185x over previous
#include <cuda_runtime.h>
#include <cuda_fp16.h>
#include <math.h>
#include <stdint.h>

// ---------------------------------------------------------------------------
// Attention_80642305950390 — round 11: fragment-level software pipelining.
// All 16 ldmatrix for a kt issued up front (latencies overlap), then 64 MMAs.
// Launch structure identical to round 10 (merged single-stream launches).
//   B=4, S=2048, E=1024, A=1024.
// ---------------------------------------------------------------------------

#define Bq 4
#define Sq 2048
#define Eq 1024
#define Aq 1024
#define MS (Bq * Sq)

__device__ __half g_qh [(size_t)MS * Eq];
__device__ __half g_kh [(size_t)MS * Eq];
__device__ __half g_vh [(size_t)MS * Eq];
__device__ __half g_Wqt[(size_t)Eq * Aq];
__device__ __half g_Wkt[(size_t)Eq * Aq];
__device__ __half g_Wvt[(size_t)Eq * Aq];
__device__ __half g_Qh [(size_t)MS * Aq];
__device__ __half g_Kh [(size_t)MS * Aq];
__device__ __half g_Vth[(size_t)MS * Aq];      // per-batch V^T [b][A][S]
__device__ __half g_Ph [(size_t)Bq * Sq * Sq];
__device__ float  g_S  [(size_t)Bq * Sq * Sq];

// ---------------------------------------------------------------------------
__device__ __forceinline__ uint32_t smem_u32(const void* p) {
    uint32_t a;
    asm("{ .reg .u64 t; cvta.to.shared.u64 t, %1; cvt.u32.u64 %0, t; }"
        : "=r"(a) : "l"(p));
    return a;
}
__device__ __forceinline__ void cp_async16(uint32_t smem, const void* gmem) {
    asm volatile("cp.async.cg.shared.global [%0], [%1], 16;\n" :: "r"(smem), "l"(gmem));
}
#define CP_COMMIT() asm volatile("cp.async.commit_group;\n" ::: "memory")
#define CP_WAIT(N)  asm volatile("cp.async.wait_group %0;\n" :: "n"(N) : "memory")

__device__ __forceinline__ void ldsm_x4(uint32_t addr, uint32_t* r) {
    asm volatile("ldmatrix.sync.aligned.m8n8.x4.shared.b16 {%0,%1,%2,%3}, [%4];"
                 : "=r"(r[0]), "=r"(r[1]), "=r"(r[2]), "=r"(r[3]) : "r"(addr));
}
__device__ __forceinline__ void mma_f16(float* d, const uint32_t* a,
                                        uint32_t b0, uint32_t b1) {
    asm volatile(
        "mma.sync.aligned.m16n8k16.row.col.f32.f16.f16.f32 "
        "{%0,%1,%2,%3},{%4,%5,%6,%7},{%8,%9},{%0,%1,%2,%3};"
        : "+f"(d[0]), "+f"(d[1]), "+f"(d[2]), "+f"(d[3])
        : "r"(a[0]), "r"(a[1]), "r"(a[2]), "r"(a[3]), "r"(b0), "r"(b1));
}

#define ROW_B 80
#define AB_PAD_BYTES (128 * ROW_B)
#define STAGE_BYTES (2 * AB_PAD_BYTES)
#define GEMM_SMEM (4 * STAGE_BYTES)           // 81920

// ---------------------------------------------------------------------------
// Shared mainloop: accumulates 128x128 tile of A[M,K] @ B[N,K]^T.
// Per kt: issue ALL 16 ldmatrix (both k16 sub-steps), then all 64 MMAs.
// ---------------------------------------------------------------------------
struct GemmCtx {
    float acc[4][8][4];
};

__device__ __forceinline__ void gemm_mainloop(
    GemmCtx& ctx, const __half* __restrict__ A, const __half* __restrict__ B,
    int K, int cRow, int cCol, uint32_t smem_base,
    int tid, uint32_t a_lane, uint32_t b_lane)
{
    #pragma unroll
    for (int i = 0; i < 4; i++)
        #pragma unroll
        for (int j = 0; j < 8; j++)
            #pragma unroll
            for (int r = 0; r < 4; r++) ctx.acc[i][j][r] = 0.0f;

    const int NK = K >> 5;

    auto load_tile = [&](int stage, int kt) {
        const uint32_t As = smem_base + stage * STAGE_BYTES;
        const uint32_t Bs = As + AB_PAD_BYTES;
        const long long kbase = (long long)(kt << 5);
        #pragma unroll
        for (int i = 0; i < 4; i++) {
            const int ch  = tid + i * 128;
            const int row = ch >> 2;
            const int k4  = ch & 3;
            const uint32_t so = (uint32_t)(row * ROW_B + k4 * 16);
            cp_async16(As + so, &A[(long long)(cRow + row) * K + kbase + k4 * 8]);
            cp_async16(Bs + so, &B[(long long)(cCol + row) * K + kbase + k4 * 8]);
        }
    };

    load_tile(0, 0); CP_COMMIT();
    load_tile(1, 1); CP_COMMIT();
    load_tile(2, 2); CP_COMMIT();

    for (int kt = 0; kt < NK; kt++) {
        CP_WAIT(2);
        __syncthreads();

        if (kt + 3 < NK) load_tile((kt + 3) & 3, kt + 3);
        CP_COMMIT();

        const uint32_t sA_base = smem_base + (kt & 3) * STAGE_BYTES + a_lane;
        const uint32_t sB_base = smem_base + (kt & 3) * STAGE_BYTES + AB_PAD_BYTES + b_lane;

        // Issue every fragment load for this kt first (latencies overlap),
        // then drain all 64 MMAs.
        uint32_t a[2][4][4], b[2][4][4];
        #pragma unroll
        for (int s = 0; s < 2; s++) {
            const uint32_t ko = s * 32;
            #pragma unroll
            for (int mi = 0; mi < 4; mi++)
                ldsm_x4(sA_base + mi * (16 * ROW_B) + ko, a[s][mi]);
            #pragma unroll
            for (int p = 0; p < 4; p++)
                ldsm_x4(sB_base + p * (16 * ROW_B) + ko, b[s][p]);
        }
        #pragma unroll
        for (int s = 0; s < 2; s++)
            #pragma unroll
            for (int p = 0; p < 4; p++)
                #pragma unroll
                for (int mi = 0; mi < 4; mi++) {
                    mma_f16(ctx.acc[mi][2 * p    ], a[s][mi], b[s][p][0], b[s][p][1]);
                    mma_f16(ctx.acc[mi][2 * p + 1], a[s][mi], b[s][p][2], b[s][p][3]);
                }
    }
}

// ---------------------------------------------------------------------------
// Merged QKV projection: grid (8, 64, 3). z: 0=Q, 1=K (half out), 2=V (half
// transposed out per batch [b][A][S]). M=8192, N=A=1024, K=E=1024, bias.
// ---------------------------------------------------------------------------
__global__ __launch_bounds__(128, 2)
void qkv_proj_kernel(const __half* __restrict__ qh, const __half* __restrict__ kh,
                     const __half* __restrict__ vh,
                     const __half* __restrict__ Wqt, const __half* __restrict__ Wkt,
                     const __half* __restrict__ Wvt,
                     const float* __restrict__ bq, const float* __restrict__ bk,
                     const float* __restrict__ bv,
                     __half* __restrict__ Qh, __half* __restrict__ Kh,
                     __half* __restrict__ Vth)
{
    extern __shared__ char smem[];
    const uint32_t smem_base = smem_u32(smem);
    const int z = blockIdx.z;

    const __half* A = (z == 0) ? qh : (z == 1) ? kh : vh;
    const __half* B = (z == 0) ? Wqt : (z == 1) ? Wkt : Wvt;
    const float* bias = (z == 0) ? bq : (z == 1) ? bk : bv;

    const int tid  = threadIdx.x;
    const int lane = tid & 31;
    const int wid  = tid >> 5;
    const int wm   = wid >> 1;
    const int wn   = wid & 1;
    const int g    = lane >> 2;
    const int t    = lane & 3;
    const int cRow = blockIdx.y * 128;
    const int cCol = blockIdx.x * 128;

    const uint32_t a_lane = (uint32_t)((wm * 64 + (lane & 15)) * ROW_B
                                       + (lane >> 4) * 16);
    const uint32_t b_lane = (uint32_t)((wn * 64 + (lane & 7) + ((lane >> 4) & 1) * 8) * ROW_B
                                       + ((lane >> 3) & 1) * 16);

    GemmCtx ctx;
    gemm_mainloop(ctx, A, B, Eq, cRow, cCol, smem_base, tid, a_lane, b_lane);

    if (z != 2) {
        __half* C = (z == 0) ? Qh : Kh;
        #pragma unroll
        for (int mi = 0; mi < 4; mi++) {
            const int row0 = cRow + wm * 64 + mi * 16 + g;
            #pragma unroll
            for (int ni = 0; ni < 8; ni++) {
                const int col = cCol + wn * 64 + ni * 8 + t * 2;
                const float2 b2 = *reinterpret_cast<const float2*>(&bias[col]);
                *reinterpret_cast<__half2*>(&C[(long long)row0 * Aq + col]) =
                    __floats2half2_rn(ctx.acc[mi][ni][0] + b2.x,
                                      ctx.acc[mi][ni][1] + b2.y);
                *reinterpret_cast<__half2*>(&C[(long long)(row0 + 8) * Aq + col]) =
                    __floats2half2_rn(ctx.acc[mi][ni][2] + b2.x,
                                      ctx.acc[mi][ni][3] + b2.y);
            }
        }
    } else {
        // Transposed half store via smem staging [n_local][m_local].
        __syncthreads();
        __half* sT = reinterpret_cast<__half*>(smem);
        const int TP = 136;
        #pragma unroll
        for (int mi = 0; mi < 4; mi++) {
            const int ml0 = wm * 64 + mi * 16 + g;
            #pragma unroll
            for (int ni = 0; ni < 8; ni++) {
                const int nl = wn * 64 + ni * 8 + t * 2;
                const float2 b2 = *reinterpret_cast<const float2*>(&bias[cCol + nl]);
                sT[(nl    ) * TP + ml0    ] = __float2half_rn(ctx.acc[mi][ni][0] + b2.x);
                sT[(nl + 1) * TP + ml0    ] = __float2half_rn(ctx.acc[mi][ni][1] + b2.y);
                sT[(nl    ) * TP + ml0 + 8] = __float2half_rn(ctx.acc[mi][ni][2] + b2.x);
                sT[(nl + 1) * TP + ml0 + 8] = __float2half_rn(ctx.acc[mi][ni][3] + b2.y);
            }
        }
        __syncthreads();
        const int b    = cRow / Sq;
        const int mloc = cRow % Sq;
        #pragma unroll
        for (int i = 0; i < 16; i++) {
            const int idx = tid + i * 128;
            const int nl  = idx >> 4;
            const int m8  = (idx & 15) * 8;
            const long long co = ((long long)b * Aq + cCol + nl) * Sq + mloc + m8;
            float4 v = *reinterpret_cast<const float4*>(&sT[nl * TP + m8]);
            *reinterpret_cast<float4*>(&Vth[co]) = v;
        }
    }
}

// ---------------------------------------------------------------------------
// Attention GEMMs (NT, no bias): fp32 out (scores / d_out).
// ---------------------------------------------------------------------------
__global__ __launch_bounds__(128, 2)
void attn_gemm_kernel(const __half* __restrict__ A, const __half* __restrict__ B,
                      float* __restrict__ C, int N, int K, float alpha,
                      long long sA, long long sB, long long sC)
{
    extern __shared__ char smem[];
    const uint32_t smem_base = smem_u32(smem);

    A += (long long)blockIdx.z * sA;
    B += (long long)blockIdx.z * sB;
    C += (long long)blockIdx.z * sC;

    const int tid  = threadIdx.x;
    const int lane = tid & 31;
    const int wid  = tid >> 5;
    const int wm   = wid >> 1;
    const int wn   = wid & 1;
    const int g    = lane >> 2;
    const int t    = lane & 3;
    const int cRow = blockIdx.y * 128;
    const int cCol = blockIdx.x * 128;

    const uint32_t a_lane = (uint32_t)((wm * 64 + (lane & 15)) * ROW_B
                                       + (lane >> 4) * 16);
    const uint32_t b_lane = (uint32_t)((wn * 64 + (lane & 7) + ((lane >> 4) & 1) * 8) * ROW_B
                                       + ((lane >> 3) & 1) * 16);

    GemmCtx ctx;
    gemm_mainloop(ctx, A, B, K, cRow, cCol, smem_base, tid, a_lane, b_lane);

    #pragma unroll
    for (int mi = 0; mi < 4; mi++) {
        const int row0 = cRow + wm * 64 + mi * 16 + g;
        #pragma unroll
        for (int ni = 0; ni < 8; ni++) {
            const int col = cCol + wn * 64 + ni * 8 + t * 2;
            float2 v0, v1;
            v0.x = ctx.acc[mi][ni][0] * alpha;
            v0.y = ctx.acc[mi][ni][1] * alpha;
            v1.x = ctx.acc[mi][ni][2] * alpha;
            v1.y = ctx.acc[mi][ni][3] * alpha;
            *reinterpret_cast<float2*>(&C[(long long)row0 * N + col]) = v0;
            *reinterpret_cast<float2*>(&C[(long long)(row0 + 8) * N + col]) = v1;
        }
    }
}

// ---------------------------------------------------------------------------
__global__ __launch_bounds__(256)
void cvt3_kernel(const float* __restrict__ in0, const float* __restrict__ in1,
                 const float* __restrict__ in2,
                 __half2* __restrict__ o0, __half2* __restrict__ o1,
                 __half2* __restrict__ o2, int n4)
{
    const int z = blockIdx.z;
    const float* in = (z == 0) ? in0 : (z == 1) ? in1 : in2;
    __half2* out = (z == 0) ? o0 : (z == 1) ? o1 : o2;
    int i = blockIdx.x * blockDim.x + threadIdx.x;
    if (i < n4) {
        float4 v = reinterpret_cast<const float4*>(in)[i];
        out[2 * i    ] = __floats2half2_rn(v.x, v.y);
        out[2 * i + 1] = __floats2half2_rn(v.z, v.w);
    }
}

__global__ __launch_bounds__(256)
void transpose3_kernel(const float* __restrict__ w0, const float* __restrict__ w1,
                       const float* __restrict__ w2,
                       __half* __restrict__ o0, __half* __restrict__ o1,
                       __half* __restrict__ o2)
{
    const int z = blockIdx.z;
    const float* in = (z == 0) ? w0 : (z == 1) ? w1 : w2;
    __half* out = (z == 0) ? o0 : (z == 1) ? o1 : o2;
    __shared__ __half tbuf[32][33];
    const int tx = threadIdx.x, ty = threadIdx.y;
    const int a0 = blockIdx.x * 32;
    const int e0 = blockIdx.y * 32;
    #pragma unroll
    for (int r = 0; r < 4; r++)
        tbuf[ty + r * 8][tx] = __float2half_rn(
            in[(long long)(e0 + ty + r * 8) * Aq + a0 + tx]);
    __syncthreads();
    #pragma unroll
    for (int r = 0; r < 4; r++)
        out[(long long)(a0 + ty + r * 8) * Eq + e0 + tx] = tbuf[tx][ty + r * 8];
}

// ---------------------------------------------------------------------------
__global__ __launch_bounds__(256)
void softmax_kernel(const float* __restrict__ S, __half* __restrict__ P)
{
    const float* row = S + (long long)blockIdx.x * Sq;
    __half* prow = P + (long long)blockIdx.x * Sq;
    const int tid  = threadIdx.x;
    const int lane = tid & 31;
    const int wid  = tid >> 5;
    __shared__ float rmax[8];
    __shared__ float rsum[8];

    float vals[8];
    float lmax = -INFINITY;
    #pragma unroll
    for (int i = 0; i < 8; i++) {
        vals[i] = row[tid + i * 256];
        lmax = fmaxf(lmax, vals[i]);
    }
    #pragma unroll
    for (int o = 16; o > 0; o >>= 1)
        lmax = fmaxf(lmax, __shfl_xor_sync(0xffffffffu, lmax, o));
    if (lane == 0) rmax[wid] = lmax;
    __syncthreads();
    if (tid < 32) {
        float m = (lane < 8) ? rmax[lane] : -INFINITY;
        #pragma unroll
        for (int o = 4; o > 0; o >>= 1)
            m = fmaxf(m, __shfl_xor_sync(0xffffffffu, m, o));
        if (lane == 0) rmax[0] = m;
    }
    __syncthreads();
    const float m = rmax[0];

    float lsum = 0.0f;
    #pragma unroll
    for (int i = 0; i < 8; i++) {
        vals[i] = expf(vals[i] - m);
        lsum += vals[i];
    }
    #pragma unroll
    for (int o = 16; o > 0; o >>= 1)
        lsum += __shfl_xor_sync(0xffffffffu, lsum, o);
    if (lane == 0) rsum[wid] = lsum;
    __syncthreads();
    if (tid < 32) {
        float s = (lane < 8) ? rsum[lane] : 0.0f;
        #pragma unroll
        for (int o = 4; o > 0; o >>= 1)
            s += __shfl_xor_sync(0xffffffffu, s, o);
        if (lane == 0) rsum[0] = s;
    }
    __syncthreads();
    const float inv = 1.0f / rsum[0];
    #pragma unroll
    for (int i = 0; i < 8; i++)
        prow[tid + i * 256] = __float2half_rn(vals[i] * inv);
}

// ---------------------------------------------------------------------------
extern "C" void kernel_launch(void* const* d_in, const int* in_sizes, int n_in,
                              void* d_out, int out_size)
{
    const float* query = (const float*)d_in[0];
    const float* key   = (const float*)d_in[1];
    const float* value = (const float*)d_in[2];
    const float* Wq    = (const float*)d_in[3];
    const float* bq    = (const float*)d_in[4];
    const float* Wk    = (const float*)d_in[5];
    const float* bk    = (const float*)d_in[6];
    const float* Wv    = (const float*)d_in[7];
    const float* bv    = (const float*)d_in[8];
    float* out = (float*)d_out;

    __half *pqh, *pkh, *pvh, *pWqt, *pWkt, *pWvt, *pQh, *pKh, *pVth, *pPh;
    float* pS;
    cudaGetSymbolAddress((void**)&pqh,  g_qh);
    cudaGetSymbolAddress((void**)&pkh,  g_kh);
    cudaGetSymbolAddress((void**)&pvh,  g_vh);
    cudaGetSymbolAddress((void**)&pWqt, g_Wqt);
    cudaGetSymbolAddress((void**)&pWkt, g_Wkt);
    cudaGetSymbolAddress((void**)&pWvt, g_Wvt);
    cudaGetSymbolAddress((void**)&pQh,  g_Qh);
    cudaGetSymbolAddress((void**)&pKh,  g_Kh);
    cudaGetSymbolAddress((void**)&pVth, g_Vth);
    cudaGetSymbolAddress((void**)&pPh,  g_Ph);
    cudaGetSymbolAddress((void**)&pS,   g_S);

    static bool attr_done = false;
    if (!attr_done) {
        cudaFuncSetAttribute(qkv_proj_kernel,
            cudaFuncAttributeMaxDynamicSharedMemorySize, GEMM_SMEM);
        cudaFuncSetAttribute(attn_gemm_kernel,
            cudaFuncAttributeMaxDynamicSharedMemorySize, GEMM_SMEM);
        attr_done = true;
    }

    const int nin = MS * Eq / 4;

    // 1) input conversions (one grid, z=3)
    cvt3_kernel<<<dim3((nin + 255) / 256, 1, 3), 256>>>(
        query, key, value, (__half2*)pqh, (__half2*)pkh, (__half2*)pvh, nin);

    // 2) weight transposes (one grid, z=3)
    transpose3_kernel<<<dim3(Aq / 32, Eq / 32, 3), dim3(32, 8)>>>(
        Wq, Wk, Wv, pWqt, pWkt, pWvt);

    // 3) QKV projections (one grid, z=3; V^T fused)
    qkv_proj_kernel<<<dim3(Aq / 128, MS / 128, 3), 128, GEMM_SMEM>>>(
        pqh, pkh, pvh, pWqt, pWkt, pWvt, bq, bk, bv, pQh, pKh, pVth);

    // 4) scores = Q @ K^T / 32 (batched z=4)
    attn_gemm_kernel<<<dim3(Sq / 128, Sq / 128, Bq), 128, GEMM_SMEM>>>(
        pQh, pKh, pS, Sq, Aq, 1.0f / 32.0f,
        (long long)Sq * Aq, (long long)Sq * Aq, (long long)Sq * Sq);

    // 5) softmax -> half probs
    softmax_kernel<<<Bq * Sq, 256>>>(pS, pPh);

    // 6) out = P @ (V^T)^T (batched z=4) -> d_out fp32
    attn_gemm_kernel<<<dim3(Aq / 128, Sq / 128, Bq), 128, GEMM_SMEM>>>(
        pPh, pVth, out, Aq, Sq, 1.0f,
        (long long)Sq * Sq, (long long)Sq * Aq, (long long)Sq * Aq);
}